// round 1
// baseline (speedup 1.0000x reference)
#include <cuda_runtime.h>
#include <math.h>

// Problem constants
#define BN 4
#define SQ 2048
#define DM 1024
#define MT (BN * SQ)   // 8192 total rows

// Scratch: q, k, v projections + score matrix (per rules: __device__ globals, no allocation)
__device__ float g_q[(long long)MT * DM];
__device__ float g_k[(long long)MT * DM];
__device__ float g_v[(long long)MT * DM];
__device__ float g_sc[(long long)BN * SQ * SQ];

// ---------------------------------------------------------------------------
// GEMM 1: projections. C[m][n] = sum_k X[m][k] * W[k][n]
// X: [8192,1024] k-contiguous; W: [1024,1024] n-contiguous.
// which: 0->g_q, 1->g_k, 2->g_v
// Tile 128x128, BK=16, 256 threads, 8x8 per thread.
// ---------------------------------------------------------------------------
__global__ __launch_bounds__(256, 2) void gemm_proj(
    const float* __restrict__ X, const float* __restrict__ W, int which)
{
    __shared__ float As[16][128];
    __shared__ float Bs[16][128];
    float* Cout = (which == 0) ? g_q : (which == 1) ? g_k : g_v;

    const int tid = threadIdx.x;
    const int bx = blockIdx.x;   // n tile (0..7)
    const int by = blockIdx.y;   // m tile (0..63)
    const int tx = tid & 15, ty = tid >> 4;

    const float* Ab = X + (size_t)by * 128 * DM;
    const float* Bb = W + bx * 128;

    float acc[8][8];
#pragma unroll
    for (int i = 0; i < 8; ++i)
#pragma unroll
        for (int j = 0; j < 8; ++j) acc[i][j] = 0.f;

    for (int kt = 0; kt < DM / 16; ++kt) {
#pragma unroll
        for (int u = 0; u < 2; ++u) {
            int f = tid + u * 256;
            int row = f >> 2, kc = (f & 3) << 2;
            float4 v = *reinterpret_cast<const float4*>(Ab + (size_t)row * DM + kt * 16 + kc);
            As[kc + 0][row] = v.x; As[kc + 1][row] = v.y;
            As[kc + 2][row] = v.z; As[kc + 3][row] = v.w;
        }
#pragma unroll
        for (int u = 0; u < 2; ++u) {
            int f = tid + u * 256;
            int k = f >> 5, n4 = (f & 31) << 2;
            *reinterpret_cast<float4*>(&Bs[k][n4]) =
                *reinterpret_cast<const float4*>(Bb + (size_t)(kt * 16 + k) * DM + n4);
        }
        __syncthreads();
#pragma unroll
        for (int k = 0; k < 16; ++k) {
            float a[8], b[8];
            *reinterpret_cast<float4*>(&a[0]) = *reinterpret_cast<const float4*>(&As[k][ty * 8]);
            *reinterpret_cast<float4*>(&a[4]) = *reinterpret_cast<const float4*>(&As[k][ty * 8 + 4]);
            *reinterpret_cast<float4*>(&b[0]) = *reinterpret_cast<const float4*>(&Bs[k][tx * 8]);
            *reinterpret_cast<float4*>(&b[4]) = *reinterpret_cast<const float4*>(&Bs[k][tx * 8 + 4]);
#pragma unroll
            for (int i = 0; i < 8; ++i)
#pragma unroll
                for (int j = 0; j < 8; ++j) acc[i][j] += a[i] * b[j];
        }
        __syncthreads();
    }

#pragma unroll
    for (int i = 0; i < 8; ++i) {
        float* cp = Cout + (size_t)(by * 128 + ty * 8 + i) * DM + bx * 128 + tx * 8;
        float4 v0 = make_float4(acc[i][0], acc[i][1], acc[i][2], acc[i][3]);
        float4 v1 = make_float4(acc[i][4], acc[i][5], acc[i][6], acc[i][7]);
        *reinterpret_cast<float4*>(cp) = v0;
        *reinterpret_cast<float4*>(cp + 4) = v1;
    }
}

// ---------------------------------------------------------------------------
// GEMM 2: scores. Sc[b][i][j] = scale * sum_d Q[b][i][d] * K[b][j][d]
// Both operands d-contiguous (NT GEMM). Causal block-skip: skip bx > by.
// ---------------------------------------------------------------------------
__global__ __launch_bounds__(256, 2) void gemm_scores()
{
    const int bx = blockIdx.x;   // j tile
    const int by = blockIdx.y;   // i tile
    const int bz = blockIdx.z;   // batch
    if (bx > by) return;         // whole tile above the diagonal

    __shared__ float As[16][128];
    __shared__ float Bs[16][128];
    const int tid = threadIdx.x;
    const int tx = tid & 15, ty = tid >> 4;

    const float* Qb = g_q + (size_t)bz * SQ * DM + (size_t)by * 128 * DM;
    const float* Kb = g_k + (size_t)bz * SQ * DM + (size_t)bx * 128 * DM;

    float acc[8][8];
#pragma unroll
    for (int i = 0; i < 8; ++i)
#pragma unroll
        for (int j = 0; j < 8; ++j) acc[i][j] = 0.f;

    for (int kt = 0; kt < DM / 16; ++kt) {
#pragma unroll
        for (int u = 0; u < 2; ++u) {
            int f = tid + u * 256;
            int row = f >> 2, kc = (f & 3) << 2;
            float4 v = *reinterpret_cast<const float4*>(Qb + (size_t)row * DM + kt * 16 + kc);
            As[kc + 0][row] = v.x; As[kc + 1][row] = v.y;
            As[kc + 2][row] = v.z; As[kc + 3][row] = v.w;
        }
#pragma unroll
        for (int u = 0; u < 2; ++u) {
            int f = tid + u * 256;
            int row = f >> 2, kc = (f & 3) << 2;
            float4 v = *reinterpret_cast<const float4*>(Kb + (size_t)row * DM + kt * 16 + kc);
            Bs[kc + 0][row] = v.x; Bs[kc + 1][row] = v.y;
            Bs[kc + 2][row] = v.z; Bs[kc + 3][row] = v.w;
        }
        __syncthreads();
#pragma unroll
        for (int k = 0; k < 16; ++k) {
            float a[8], b[8];
            *reinterpret_cast<float4*>(&a[0]) = *reinterpret_cast<const float4*>(&As[k][ty * 8]);
            *reinterpret_cast<float4*>(&a[4]) = *reinterpret_cast<const float4*>(&As[k][ty * 8 + 4]);
            *reinterpret_cast<float4*>(&b[0]) = *reinterpret_cast<const float4*>(&Bs[k][tx * 8]);
            *reinterpret_cast<float4*>(&b[4]) = *reinterpret_cast<const float4*>(&Bs[k][tx * 8 + 4]);
#pragma unroll
            for (int i = 0; i < 8; ++i)
#pragma unroll
                for (int j = 0; j < 8; ++j) acc[i][j] += a[i] * b[j];
        }
        __syncthreads();
    }

    const float scale = 0.03125f;  // 1/sqrt(1024)
    float* Cb = g_sc + (size_t)bz * SQ * SQ;
#pragma unroll
    for (int i = 0; i < 8; ++i) {
        float* cp = Cb + (size_t)(by * 128 + ty * 8 + i) * SQ + bx * 128 + tx * 8;
        float4 v0 = make_float4(acc[i][0] * scale, acc[i][1] * scale,
                                acc[i][2] * scale, acc[i][3] * scale);
        float4 v1 = make_float4(acc[i][4] * scale, acc[i][5] * scale,
                                acc[i][6] * scale, acc[i][7] * scale);
        *reinterpret_cast<float4*>(cp) = v0;
        *reinterpret_cast<float4*>(cp + 4) = v1;
    }
}

// ---------------------------------------------------------------------------
// Causal row softmax in place; zeros above-diagonal so PV can be dense.
// One block (256 threads) per row. grid = 8192.
// ---------------------------------------------------------------------------
__global__ __launch_bounds__(256) void softmax_causal()
{
    const int row = blockIdx.x;
    const int b = row >> 11;           // row / SQ
    const int i = row & (SQ - 1);
    float* p = g_sc + ((size_t)b * SQ + i) * SQ;
    const int n = i + 1;
    const int tid = threadIdx.x;
    __shared__ float red[256];

    float mx = -1e30f;
    for (int j = tid; j < n; j += 256) mx = fmaxf(mx, p[j]);
    red[tid] = mx; __syncthreads();
    for (int s2 = 128; s2 > 0; s2 >>= 1) {
        if (tid < s2) red[tid] = fmaxf(red[tid], red[tid + s2]);
        __syncthreads();
    }
    mx = red[0];
    __syncthreads();

    float sum = 0.f;
    for (int j = tid; j < n; j += 256) {
        float e = __expf(p[j] - mx);
        p[j] = e;
        sum += e;
    }
    red[tid] = sum; __syncthreads();
    for (int s2 = 128; s2 > 0; s2 >>= 1) {
        if (tid < s2) red[tid] += red[tid + s2];
        __syncthreads();
    }
    const float inv = 1.f / red[0];

    for (int j = tid; j < n; j += 256) p[j] *= inv;
    for (int j = n + tid; j < SQ; j += 256) p[j] = 0.f;
}

// ---------------------------------------------------------------------------
// GEMM 3: context = weights @ V. out[b][i][e] = sum_j W[b][i][j] * V[b][j][e]
// Causal k-loop truncation: k-tiles only up to (by+1)*8.
// ---------------------------------------------------------------------------
__global__ __launch_bounds__(256, 2) void gemm_pv(float* __restrict__ out)
{
    __shared__ float As[16][128];
    __shared__ float Bs[16][128];
    const int tid = threadIdx.x;
    const int bx = blockIdx.x;   // e tile (0..7)
    const int by = blockIdx.y;   // i tile (0..15)
    const int bz = blockIdx.z;   // batch
    const int tx = tid & 15, ty = tid >> 4;

    const float* Ab = g_sc + (size_t)bz * SQ * SQ + (size_t)by * 128 * SQ;  // weights, j-contig
    const float* Bb = g_v + (size_t)bz * SQ * DM + bx * 128;                // V, e-contig

    float acc[8][8];
#pragma unroll
    for (int i = 0; i < 8; ++i)
#pragma unroll
        for (int j = 0; j < 8; ++j) acc[i][j] = 0.f;

    const int kTiles = (by + 1) * 8;   // j only up to diagonal of this i-tile
    for (int kt = 0; kt < kTiles; ++kt) {
#pragma unroll
        for (int u = 0; u < 2; ++u) {
            int f = tid + u * 256;
            int row = f >> 2, kc = (f & 3) << 2;
            float4 v = *reinterpret_cast<const float4*>(Ab + (size_t)row * SQ + kt * 16 + kc);
            As[kc + 0][row] = v.x; As[kc + 1][row] = v.y;
            As[kc + 2][row] = v.z; As[kc + 3][row] = v.w;
        }
#pragma unroll
        for (int u = 0; u < 2; ++u) {
            int f = tid + u * 256;
            int k = f >> 5, n4 = (f & 31) << 2;
            *reinterpret_cast<float4*>(&Bs[k][n4]) =
                *reinterpret_cast<const float4*>(Bb + (size_t)(kt * 16 + k) * DM + n4);
        }
        __syncthreads();
#pragma unroll
        for (int k = 0; k < 16; ++k) {
            float a[8], b[8];
            *reinterpret_cast<float4*>(&a[0]) = *reinterpret_cast<const float4*>(&As[k][ty * 8]);
            *reinterpret_cast<float4*>(&a[4]) = *reinterpret_cast<const float4*>(&As[k][ty * 8 + 4]);
            *reinterpret_cast<float4*>(&b[0]) = *reinterpret_cast<const float4*>(&Bs[k][tx * 8]);
            *reinterpret_cast<float4*>(&b[4]) = *reinterpret_cast<const float4*>(&Bs[k][tx * 8 + 4]);
#pragma unroll
            for (int i = 0; i < 8; ++i)
#pragma unroll
                for (int j = 0; j < 8; ++j) acc[i][j] += a[i] * b[j];
        }
        __syncthreads();
    }

#pragma unroll
    for (int i = 0; i < 8; ++i) {
        float* cp = out + (size_t)bz * SQ * DM
                        + (size_t)(by * 128 + ty * 8 + i) * DM + bx * 128 + tx * 8;
        float4 v0 = make_float4(acc[i][0], acc[i][1], acc[i][2], acc[i][3]);
        float4 v1 = make_float4(acc[i][4], acc[i][5], acc[i][6], acc[i][7]);
        *reinterpret_cast<float4*>(cp) = v0;
        *reinterpret_cast<float4*>(cp + 4) = v1;
    }
}

// ---------------------------------------------------------------------------
extern "C" void kernel_launch(void* const* d_in, const int* in_sizes, int n_in,
                              void* d_out, int out_size)
{
    const float* x  = (const float*)d_in[0];
    const float* Wq = (const float*)d_in[1];
    const float* Wk = (const float*)d_in[2];
    const float* Wv = (const float*)d_in[3];
    float* out = (float*)d_out;

    dim3 blk(256);
    dim3 gProj(DM / 128, MT / 128);        // (8, 64)
    gemm_proj<<<gProj, blk>>>(x, Wq, 0);
    gemm_proj<<<gProj, blk>>>(x, Wk, 1);
    gemm_proj<<<gProj, blk>>>(x, Wv, 2);

    dim3 gSc(SQ / 128, SQ / 128, BN);      // (16, 16, 4)
    gemm_scores<<<gSc, blk>>>();

    softmax_causal<<<MT, blk>>>();

    dim3 gPV(DM / 128, SQ / 128, BN);      // (8, 16, 4)
    gemm_pv<<<gPV, blk>>>(out);
}

// round 3
// speedup vs baseline: 3.4185x; 3.4185x over previous
#include <cuda_runtime.h>
#include <cstdint>

#define BN 4
#define SQ 2048
#define DM 1024
#define MT (BN * SQ)
#define BK 32
#define APAD 36          // floats per A-tile row (128B data + pad; 144B, 16B-aligned)
#define BPAD 136         // floats per B-tile row (512B data + pad; 544B, 16B-aligned)
#define ABYTES (128 * APAD * 4)      // 18432
#define BBYTES_MAX 18432             // max(128*36, 32*136)*4
#define STAGE (ABYTES + BBYTES_MAX)  // 36864
#define SMEM_DYN (2 * STAGE)         // 73728

// Scratch (__device__ globals; no allocation allowed)
__device__ float g_x[(size_t)MT * DM];        // tf32-rounded input
__device__ float g_w[(size_t)3 * DM * DM];    // tf32-rounded Wq|Wk|Wv
__device__ float g_q[(size_t)MT * DM];
__device__ float g_k[(size_t)MT * DM];
__device__ float g_v[(size_t)MT * DM];
__device__ float g_sc[(size_t)BN * SQ * SQ];

// ---------------------------------------------------------------------------
__device__ __forceinline__ uint32_t smem_u32(const void* p) {
    uint32_t a;
    asm("{ .reg .u64 t; cvta.to.shared.u64 t, %1; cvt.u32.u64 %0, t; }" : "=r"(a) : "l"(p));
    return a;
}

__device__ __forceinline__ float tf32r(float x) {
    uint32_t u;
    asm("cvt.rna.tf32.f32 %0, %1;" : "=r"(u) : "f"(x));
    return __uint_as_float(u);
}

#define CP16(sa, g) \
    asm volatile("cp.async.cg.shared.global [%0], [%1], 16;" :: "r"(sa), "l"(g))
#define CP_COMMIT() asm volatile("cp.async.commit_group;" ::: "memory")
#define CP_WAIT1()  asm volatile("cp.async.wait_group 1;" ::: "memory")

__device__ __forceinline__ void mma_tf32(float& c0, float& c1, float& c2, float& c3,
                                         uint32_t a0, uint32_t a1, uint32_t a2, uint32_t a3,
                                         uint32_t b0, uint32_t b1) {
    asm volatile(
        "mma.sync.aligned.m16n8k8.row.col.f32.tf32.tf32.f32 "
        "{%0,%1,%2,%3}, {%4,%5,%6,%7}, {%8,%9}, {%0,%1,%2,%3};"
        : "+f"(c0), "+f"(c1), "+f"(c2), "+f"(c3)
        : "r"(a0), "r"(a1), "r"(a2), "r"(a3), "r"(b0), "r"(b1));
}

// ---------------------------------------------------------------------------
// Unified tensor-core tf32 GEMM (mma.sync fallback path — tcgen05 is rejected
// by this harness's ptxas target).
// MODE: 0/1/2 = projections Q/K/V; 3 = scores (causal skip + scale);
//       4 = PV (causal K-trunc, writes final out).
// C tile 128x128, BK=32, 256 threads; warp grid 2x4, warp tile 64x32.
// BTRANS (MODE==3): B source is k-contiguous (NT gemm) -> store B tile
// k-major [n][APAD]; fragment gathers stay bank-conflict-free.
// ---------------------------------------------------------------------------
template <int MODE>
__global__ __launch_bounds__(256) void mm_mma(float* __restrict__ Out)
{
    const int bx = blockIdx.x, by = blockIdx.y, bz = blockIdx.z;
    if (MODE == 3 && bx > by) return;

    constexpr bool BT = (MODE == 3);

    const float* Ab;
    const float* Bb;
    size_t lda, ldb;
    int nt;
    if (MODE <= 2) {
        Ab = g_x + (size_t)by * 128 * DM;                        lda = DM;
        Bb = g_w + (size_t)MODE * DM * DM + bx * 128;            ldb = DM;  // [k][n]
        nt = DM / BK;
    } else if (MODE == 3) {
        Ab = g_q + ((size_t)bz * SQ + by * 128) * DM;            lda = DM;
        Bb = g_k + ((size_t)bz * SQ + bx * 128) * DM;            ldb = DM;  // [n][k]
        nt = DM / BK;
    } else {
        Ab = g_sc + ((size_t)bz * SQ + by * 128) * SQ;           lda = SQ;
        Bb = g_v + ((size_t)bz * SQ) * DM + bx * 128;            ldb = DM;  // [k][n]
        nt = (by + 1) * 4;
    }

    extern __shared__ char dsm[];
    const uint32_t sbase = smem_u32(dsm);

    const int tid = threadIdx.x;
    const int lane = tid & 31, wid = tid >> 5;
    const int wm = wid >> 2, wn = wid & 3;

    float acc[4][4][4];
#pragma unroll
    for (int i = 0; i < 4; ++i)
#pragma unroll
        for (int j = 0; j < 4; ++j)
#pragma unroll
            for (int r = 0; r < 4; ++r) acc[i][j][r] = 0.f;

    // ---- staging lambdas -------------------------------------------------
    auto stageA = [&](int kt, int buf) {
        const uint32_t abase = sbase + buf * STAGE;
#pragma unroll
        for (int u = 0; u < 4; ++u) {
            const int idx = tid + u * 256;          // 0..1023
            const int row = idx >> 3, c4 = idx & 7;
            CP16(abase + (uint32_t)(row * APAD + c4 * 4) * 4,
                 Ab + (size_t)row * lda + kt * BK + c4 * 4);
        }
    };
    auto stageB = [&](int kt, int buf) {
        const uint32_t bbase = sbase + buf * STAGE + ABYTES;
        if (BT) {
#pragma unroll
            for (int u = 0; u < 4; ++u) {
                const int idx = tid + u * 256;
                const int row = idx >> 3, c4 = idx & 7;   // row = n, c4*4 = k
                CP16(bbase + (uint32_t)(row * APAD + c4 * 4) * 4,
                     Bb + (size_t)row * ldb + kt * BK + c4 * 4);
            }
        } else {
#pragma unroll
            for (int u = 0; u < 4; ++u) {
                const int idx = tid + u * 256;
                const int k = idx >> 5, n4 = idx & 31;
                CP16(bbase + (uint32_t)(k * BPAD + n4 * 4) * 4,
                     Bb + (size_t)(kt * BK + k) * ldb + n4 * 4);
            }
        }
    };

    stageA(0, 0); stageB(0, 0);
    CP_COMMIT();

    const int ar = wm * 64 + (lane >> 2);   // A frag row base
    const int ac = lane & 3;                // A frag k base
    const int bn = wn * 32 + (lane >> 2);   // B frag n base
    const int bk = lane & 3;                // B frag k base

    for (int kt = 0; kt < nt; ++kt) {
        if (kt + 1 < nt) { stageA(kt + 1, (kt + 1) & 1); stageB(kt + 1, (kt + 1) & 1); }
        CP_COMMIT();
        CP_WAIT1();
        __syncthreads();

        const uint32_t* As = (const uint32_t*)(dsm + (kt & 1) * STAGE);
        const uint32_t* Bs = (const uint32_t*)(dsm + (kt & 1) * STAGE + ABYTES);

#pragma unroll
        for (int ks = 0; ks < 4; ++ks) {
            uint32_t af[4][4];
#pragma unroll
            for (int ma = 0; ma < 4; ++ma) {
                const int r0 = ar + ma * 16;
                af[ma][0] = As[(r0    ) * APAD + ks * 8 + ac    ];
                af[ma][1] = As[(r0 + 8) * APAD + ks * 8 + ac    ];
                af[ma][2] = As[(r0    ) * APAD + ks * 8 + ac + 4];
                af[ma][3] = As[(r0 + 8) * APAD + ks * 8 + ac + 4];
            }
            uint32_t bf[4][2];
#pragma unroll
            for (int na = 0; na < 4; ++na) {
                if (BT) {
                    const int n0 = bn + na * 8;
                    bf[na][0] = Bs[n0 * APAD + ks * 8 + bk    ];
                    bf[na][1] = Bs[n0 * APAD + ks * 8 + bk + 4];
                } else {
                    const int n0 = bn + na * 8;
                    bf[na][0] = Bs[(ks * 8 + bk    ) * BPAD + n0];
                    bf[na][1] = Bs[(ks * 8 + bk + 4) * BPAD + n0];
                }
            }
#pragma unroll
            for (int ma = 0; ma < 4; ++ma)
#pragma unroll
                for (int na = 0; na < 4; ++na)
                    mma_tf32(acc[ma][na][0], acc[ma][na][1], acc[ma][na][2], acc[ma][na][3],
                             af[ma][0], af[ma][1], af[ma][2], af[ma][3],
                             bf[na][0], bf[na][1]);
        }
        __syncthreads();
    }

    // ---- epilogue --------------------------------------------------------
    const float scale = 0.03125f;  // 1/sqrt(1024)
#pragma unroll
    for (int ma = 0; ma < 4; ++ma) {
#pragma unroll
        for (int na = 0; na < 4; ++na) {
            const int r0 = by * 128 + wm * 64 + ma * 16 + (lane >> 2);
            const int c0 = bx * 128 + wn * 32 + na * 8 + (lane & 3) * 2;
            float v0 = acc[ma][na][0], v1 = acc[ma][na][1];
            float v2 = acc[ma][na][2], v3 = acc[ma][na][3];

            if (MODE <= 2) {
                float* C = (MODE == 0) ? g_q : (MODE == 1) ? g_k : g_v;
                float2 p0 = make_float2(tf32r(v0), tf32r(v1));
                float2 p1 = make_float2(tf32r(v2), tf32r(v3));
                *reinterpret_cast<float2*>(C + (size_t)r0 * DM + c0) = p0;
                *reinterpret_cast<float2*>(C + (size_t)(r0 + 8) * DM + c0) = p1;
            } else if (MODE == 3) {
                float* C = g_sc + (size_t)bz * SQ * SQ;
                float2 p0 = make_float2(v0 * scale, v1 * scale);
                float2 p1 = make_float2(v2 * scale, v3 * scale);
                *reinterpret_cast<float2*>(C + (size_t)r0 * SQ + c0) = p0;
                *reinterpret_cast<float2*>(C + (size_t)(r0 + 8) * SQ + c0) = p1;
            } else {
                float* C = Out + (size_t)bz * SQ * DM;
                *reinterpret_cast<float2*>(C + (size_t)r0 * DM + c0) = make_float2(v0, v1);
                *reinterpret_cast<float2*>(C + (size_t)(r0 + 8) * DM + c0) = make_float2(v2, v3);
            }
        }
    }
}

// ---------------------------------------------------------------------------
// tf32 pre-rounding: dst[i] = round_rna_tf32(src[i]), vectorized
// ---------------------------------------------------------------------------
__global__ __launch_bounds__(256) void round4(const float4* __restrict__ src,
                                              float4* __restrict__ dst)
{
    const int i = blockIdx.x * 256 + threadIdx.x;
    float4 v = src[i];
    v.x = tf32r(v.x); v.y = tf32r(v.y); v.z = tf32r(v.z); v.w = tf32r(v.w);
    dst[i] = v;
}

// ---------------------------------------------------------------------------
// Causal row softmax in place; rounds weights to tf32; zeros above-diagonal.
// ---------------------------------------------------------------------------
__global__ __launch_bounds__(256) void softmax_causal()
{
    const int row = blockIdx.x;
    const int b = row >> 11;
    const int i = row & (SQ - 1);
    float* p = g_sc + ((size_t)b * SQ + i) * SQ;
    const int n = i + 1;
    const int tid = threadIdx.x;
    __shared__ float red[256];

    float mx = -1e30f;
    for (int j = tid; j < n; j += 256) mx = fmaxf(mx, p[j]);
    red[tid] = mx; __syncthreads();
    for (int s2 = 128; s2 > 0; s2 >>= 1) {
        if (tid < s2) red[tid] = fmaxf(red[tid], red[tid + s2]);
        __syncthreads();
    }
    mx = red[0];
    __syncthreads();

    float sum = 0.f;
    for (int j = tid; j < n; j += 256) {
        float e = __expf(p[j] - mx);
        p[j] = e;
        sum += e;
    }
    red[tid] = sum; __syncthreads();
    for (int s2 = 128; s2 > 0; s2 >>= 1) {
        if (tid < s2) red[tid] += red[tid + s2];
        __syncthreads();
    }
    const float inv = 1.f / red[0];

    for (int j = tid; j < n; j += 256) p[j] = tf32r(p[j] * inv);
    for (int j = n + tid; j < SQ; j += 256) p[j] = 0.f;
}

// ---------------------------------------------------------------------------
extern "C" void kernel_launch(void* const* d_in, const int* in_sizes, int n_in,
                              void* d_out, int out_size)
{
    const float* x  = (const float*)d_in[0];
    const float* Wq = (const float*)d_in[1];
    const float* Wk = (const float*)d_in[2];
    const float* Wv = (const float*)d_in[3];
    float* out = (float*)d_out;

    (void)cudaFuncSetAttribute(mm_mma<0>, cudaFuncAttributeMaxDynamicSharedMemorySize, SMEM_DYN);
    (void)cudaFuncSetAttribute(mm_mma<1>, cudaFuncAttributeMaxDynamicSharedMemorySize, SMEM_DYN);
    (void)cudaFuncSetAttribute(mm_mma<2>, cudaFuncAttributeMaxDynamicSharedMemorySize, SMEM_DYN);
    (void)cudaFuncSetAttribute(mm_mma<3>, cudaFuncAttributeMaxDynamicSharedMemorySize, SMEM_DYN);
    (void)cudaFuncSetAttribute(mm_mma<4>, cudaFuncAttributeMaxDynamicSharedMemorySize, SMEM_DYN);

    float* gx = nullptr; float* gw = nullptr;
    cudaGetSymbolAddress((void**)&gx, g_x);
    cudaGetSymbolAddress((void**)&gw, g_w);

    dim3 blk(256);
    round4<<<(MT * DM / 4) / 256, blk>>>((const float4*)x, (float4*)gx);
    round4<<<(DM * DM / 4) / 256, blk>>>((const float4*)Wq, (float4*)gw);
    round4<<<(DM * DM / 4) / 256, blk>>>((const float4*)Wk, (float4*)(gw + (size_t)DM * DM));
    round4<<<(DM * DM / 4) / 256, blk>>>((const float4*)Wv, (float4*)(gw + (size_t)2 * DM * DM));

    dim3 gProj(DM / 128, MT / 128);            // (8, 64)
    mm_mma<0><<<gProj, blk, SMEM_DYN>>>(nullptr);
    mm_mma<1><<<gProj, blk, SMEM_DYN>>>(nullptr);
    mm_mma<2><<<gProj, blk, SMEM_DYN>>>(nullptr);

    dim3 gSc(SQ / 128, SQ / 128, BN);          // (16, 16, 4)
    mm_mma<3><<<gSc, blk, SMEM_DYN>>>(nullptr);

    softmax_causal<<<MT, blk>>>();

    dim3 gPV(DM / 128, SQ / 128, BN);          // (8, 16, 4)
    mm_mma<4><<<gPV, blk, SMEM_DYN>>>(out);
}

// round 4
// speedup vs baseline: 3.6631x; 1.0716x over previous
#include <cuda_runtime.h>
#include <cstdint>

#define BN 4
#define SQ 2048
#define DM 1024
#define MT (BN * SQ)
#define BK 32
#define APAD 36          // floats per A-tile row (128B data + pad; 144B, 16B-aligned)
#define BPAD 136         // floats per B-tile row (512B data + pad; 544B, 16B-aligned)
#define ABYTES (128 * APAD * 4)      // 18432
#define BBYTES_MAX 18432             // max(128*36, 32*136)*4
#define STAGE (ABYTES + BBYTES_MAX)  // 36864
#define SMEM_DYN (2 * STAGE)         // 73728

// Scratch (__device__ globals; no allocation allowed)
__device__ float g_x[(size_t)MT * DM];        // tf32-rounded input
__device__ float g_w[(size_t)3 * DM * DM];    // tf32-rounded Wq|Wk|Wv
__device__ float g_q[(size_t)MT * DM];
__device__ float g_k[(size_t)MT * DM];
__device__ float g_v[(size_t)MT * DM];
__device__ float g_sc[(size_t)BN * SQ * SQ];  // unnormalized exp weights
__device__ float g_lp[(size_t)MT * 64];       // per-(jtile,warpcol) row-sum partials
__device__ float g_l[(size_t)MT];             // row sums

// ---------------------------------------------------------------------------
__device__ __forceinline__ uint32_t smem_u32(const void* p) {
    uint32_t a;
    asm("{ .reg .u64 t; cvta.to.shared.u64 t, %1; cvt.u32.u64 %0, t; }" : "=r"(a) : "l"(p));
    return a;
}

__device__ __forceinline__ float tf32r(float x) {
    uint32_t u;
    asm("cvt.rna.tf32.f32 %0, %1;" : "=r"(u) : "f"(x));
    return __uint_as_float(u);
}

#define CP16(sa, g) \
    asm volatile("cp.async.cg.shared.global [%0], [%1], 16;" :: "r"(sa), "l"(g))
#define CP_COMMIT() asm volatile("cp.async.commit_group;" ::: "memory")
#define CP_WAIT1()  asm volatile("cp.async.wait_group 1;" ::: "memory")

__device__ __forceinline__ void mma_tf32(float& c0, float& c1, float& c2, float& c3,
                                         uint32_t a0, uint32_t a1, uint32_t a2, uint32_t a3,
                                         uint32_t b0, uint32_t b1) {
    asm volatile(
        "mma.sync.aligned.m16n8k8.row.col.f32.tf32.tf32.f32 "
        "{%0,%1,%2,%3}, {%4,%5,%6,%7}, {%8,%9}, {%0,%1,%2,%3};"
        : "+f"(c0), "+f"(c1), "+f"(c2), "+f"(c3)
        : "r"(a0), "r"(a1), "r"(a2), "r"(a3), "r"(b0), "r"(b1));
}

// ---------------------------------------------------------------------------
// Unified tensor-core tf32 GEMM (mma.sync path; tcgen05 rejected by harness
// ptxas target).
// MODE: 0/1/2 = projections Q/K/V; 3 = scores (causal skip + exp + rowsum
//       partials); 4 = PV (causal K-trunc, row-normalize, write out).
// C tile 128x128, BK=32, 256 threads; warp grid 2x4, warp tile 64x32.
// ---------------------------------------------------------------------------
template <int MODE>
__global__ __launch_bounds__(256) void mm_mma(float* __restrict__ Out)
{
    const int bx = blockIdx.x, bz = blockIdx.z;
    // PV: launch heavy i-tiles first (cost ~ by+1) to avoid a long tail wave.
    const int by = (MODE == 4) ? ((int)gridDim.y - 1 - (int)blockIdx.y)
                               : (int)blockIdx.y;
    if (MODE == 3 && bx > by) return;

    constexpr bool BT = (MODE == 3);

    const float* Ab;
    const float* Bb;
    size_t lda, ldb;
    int nt;
    if (MODE <= 2) {
        Ab = g_x + (size_t)by * 128 * DM;                        lda = DM;
        Bb = g_w + (size_t)MODE * DM * DM + bx * 128;            ldb = DM;  // [k][n]
        nt = DM / BK;
    } else if (MODE == 3) {
        Ab = g_q + ((size_t)bz * SQ + by * 128) * DM;            lda = DM;
        Bb = g_k + ((size_t)bz * SQ + bx * 128) * DM;            ldb = DM;  // [n][k]
        nt = DM / BK;
    } else {
        Ab = g_sc + ((size_t)bz * SQ + by * 128) * SQ;           lda = SQ;
        Bb = g_v + ((size_t)bz * SQ) * DM + bx * 128;            ldb = DM;  // [k][n]
        nt = (by + 1) * 4;
    }

    extern __shared__ char dsm[];
    const uint32_t sbase = smem_u32(dsm);

    const int tid = threadIdx.x;
    const int lane = tid & 31, wid = tid >> 5;
    const int wm = wid >> 2, wn = wid & 3;

    float acc[4][4][4];
#pragma unroll
    for (int i = 0; i < 4; ++i)
#pragma unroll
        for (int j = 0; j < 4; ++j)
#pragma unroll
            for (int r = 0; r < 4; ++r) acc[i][j][r] = 0.f;

    // ---- staging ---------------------------------------------------------
    auto stageA = [&](int kt, int buf) {
        const uint32_t abase = sbase + buf * STAGE;
#pragma unroll
        for (int u = 0; u < 4; ++u) {
            const int idx = tid + u * 256;          // 0..1023
            const int row = idx >> 3, c4 = idx & 7;
            CP16(abase + (uint32_t)(row * APAD + c4 * 4) * 4,
                 Ab + (size_t)row * lda + kt * BK + c4 * 4);
        }
    };
    auto stageB = [&](int kt, int buf) {
        const uint32_t bbase = sbase + buf * STAGE + ABYTES;
        if (BT) {
#pragma unroll
            for (int u = 0; u < 4; ++u) {
                const int idx = tid + u * 256;
                const int row = idx >> 3, c4 = idx & 7;   // row = n, c4*4 = k
                CP16(bbase + (uint32_t)(row * APAD + c4 * 4) * 4,
                     Bb + (size_t)row * ldb + kt * BK + c4 * 4);
            }
        } else {
#pragma unroll
            for (int u = 0; u < 4; ++u) {
                const int idx = tid + u * 256;
                const int k = idx >> 5, n4 = idx & 31;
                CP16(bbase + (uint32_t)(k * BPAD + n4 * 4) * 4,
                     Bb + (size_t)(kt * BK + k) * ldb + n4 * 4);
            }
        }
    };

    stageA(0, 0); stageB(0, 0);
    CP_COMMIT();

    const int ar = wm * 64 + (lane >> 2);   // A frag row base
    const int ac = lane & 3;                // A frag k base
    const int bn = wn * 32 + (lane >> 2);   // B frag n base
    const int bk = lane & 3;                // B frag k base

    for (int kt = 0; kt < nt; ++kt) {
        if (kt + 1 < nt) { stageA(kt + 1, (kt + 1) & 1); stageB(kt + 1, (kt + 1) & 1); }
        CP_COMMIT();
        CP_WAIT1();
        __syncthreads();

        const uint32_t* As = (const uint32_t*)(dsm + (kt & 1) * STAGE);
        const uint32_t* Bs = (const uint32_t*)(dsm + (kt & 1) * STAGE + ABYTES);

#pragma unroll
        for (int ks = 0; ks < 4; ++ks) {
            uint32_t af[4][4];
#pragma unroll
            for (int ma = 0; ma < 4; ++ma) {
                const int r0 = ar + ma * 16;
                af[ma][0] = As[(r0    ) * APAD + ks * 8 + ac    ];
                af[ma][1] = As[(r0 + 8) * APAD + ks * 8 + ac    ];
                af[ma][2] = As[(r0    ) * APAD + ks * 8 + ac + 4];
                af[ma][3] = As[(r0 + 8) * APAD + ks * 8 + ac + 4];
            }
            uint32_t bf[4][2];
#pragma unroll
            for (int na = 0; na < 4; ++na) {
                if (BT) {
                    const int n0 = bn + na * 8;
                    bf[na][0] = Bs[n0 * APAD + ks * 8 + bk    ];
                    bf[na][1] = Bs[n0 * APAD + ks * 8 + bk + 4];
                } else {
                    const int n0 = bn + na * 8;
                    bf[na][0] = Bs[(ks * 8 + bk    ) * BPAD + n0];
                    bf[na][1] = Bs[(ks * 8 + bk + 4) * BPAD + n0];
                }
            }
#pragma unroll
            for (int ma = 0; ma < 4; ++ma)
#pragma unroll
                for (int na = 0; na < 4; ++na)
                    mma_tf32(acc[ma][na][0], acc[ma][na][1], acc[ma][na][2], acc[ma][na][3],
                             af[ma][0], af[ma][1], af[ma][2], af[ma][3],
                             bf[na][0], bf[na][1]);
        }
        __syncthreads();
    }

    // ---- epilogue --------------------------------------------------------
    if (MODE == 3) {
        // p = tf32r(exp(s*scale - 8)), causal mask on diagonal block,
        // per-warp row-sum partials -> g_lp[row][bx*4+wn] (deterministic).
        const float scale = 0.03125f;  // 1/sqrt(1024)
        float* C = g_sc + (size_t)bz * SQ * SQ;
#pragma unroll
        for (int ma = 0; ma < 4; ++ma) {
            const int rl0 = by * 128 + wm * 64 + ma * 16 + (lane >> 2);
            const int rl1 = rl0 + 8;
            float part0 = 0.f, part1 = 0.f;
#pragma unroll
            for (int na = 0; na < 4; ++na) {
                const int c0 = bx * 128 + wn * 32 + na * 8 + (lane & 3) * 2;
                float p00 = __expf(acc[ma][na][0] * scale - 8.f);
                float p01 = __expf(acc[ma][na][1] * scale - 8.f);
                float p10 = __expf(acc[ma][na][2] * scale - 8.f);
                float p11 = __expf(acc[ma][na][3] * scale - 8.f);
                if (bx == by) {
                    if (c0     > rl0) p00 = 0.f;
                    if (c0 + 1 > rl0) p01 = 0.f;
                    if (c0     > rl1) p10 = 0.f;
                    if (c0 + 1 > rl1) p11 = 0.f;
                }
                p00 = tf32r(p00); p01 = tf32r(p01);
                p10 = tf32r(p10); p11 = tf32r(p11);
                part0 += p00 + p01;
                part1 += p10 + p11;
                *reinterpret_cast<float2*>(C + (size_t)rl0 * SQ + c0) = make_float2(p00, p01);
                *reinterpret_cast<float2*>(C + (size_t)rl1 * SQ + c0) = make_float2(p10, p11);
            }
            part0 += __shfl_xor_sync(0xffffffffu, part0, 1);
            part0 += __shfl_xor_sync(0xffffffffu, part0, 2);
            part1 += __shfl_xor_sync(0xffffffffu, part1, 1);
            part1 += __shfl_xor_sync(0xffffffffu, part1, 2);
            if ((lane & 3) == 0) {
                const int idx = bx * 4 + wn;
                g_lp[(size_t)(bz * SQ + rl0) * 64 + idx] = part0;
                g_lp[(size_t)(bz * SQ + rl1) * 64 + idx] = part1;
            }
        }
        return;
    }

#pragma unroll
    for (int ma = 0; ma < 4; ++ma) {
        const int r0 = by * 128 + wm * 64 + ma * 16 + (lane >> 2);
        float inv0 = 1.f, inv1 = 1.f;
        if (MODE == 4) {
            inv0 = __fdividef(1.f, g_l[bz * SQ + r0]);
            inv1 = __fdividef(1.f, g_l[bz * SQ + r0 + 8]);
        }
#pragma unroll
        for (int na = 0; na < 4; ++na) {
            const int c0 = bx * 128 + wn * 32 + na * 8 + (lane & 3) * 2;
            float v0 = acc[ma][na][0], v1 = acc[ma][na][1];
            float v2 = acc[ma][na][2], v3 = acc[ma][na][3];

            if (MODE <= 2) {
                float* C = (MODE == 0) ? g_q : (MODE == 1) ? g_k : g_v;
                float2 p0 = make_float2(tf32r(v0), tf32r(v1));
                float2 p1 = make_float2(tf32r(v2), tf32r(v3));
                *reinterpret_cast<float2*>(C + (size_t)r0 * DM + c0) = p0;
                *reinterpret_cast<float2*>(C + (size_t)(r0 + 8) * DM + c0) = p1;
            } else {
                float* C = Out + (size_t)bz * SQ * DM;
                *reinterpret_cast<float2*>(C + (size_t)r0 * DM + c0) =
                    make_float2(v0 * inv0, v1 * inv0);
                *reinterpret_cast<float2*>(C + (size_t)(r0 + 8) * DM + c0) =
                    make_float2(v2 * inv1, v3 * inv1);
            }
        }
    }
}

// ---------------------------------------------------------------------------
// Deterministic row-sum reduce: g_l[row] = sum of valid partials (fixed order)
// ---------------------------------------------------------------------------
__global__ __launch_bounds__(256) void rowsum_reduce()
{
    const int row = blockIdx.x * 256 + threadIdx.x;   // 0..8191
    const int i = row & (SQ - 1);
    const int nvalid = ((i >> 7) + 1) * 4;            // 4*(by+1) warp-col partials
    const float* p = g_lp + (size_t)row * 64;
    float s = 0.f;
    for (int j = 0; j < nvalid; ++j) s += p[j];
    g_l[row] = s;
}

// ---------------------------------------------------------------------------
// tf32 pre-rounding: dst[i] = round_rna_tf32(src[i])
// ---------------------------------------------------------------------------
__global__ __launch_bounds__(256) void round4(const float4* __restrict__ src,
                                              float4* __restrict__ dst)
{
    const int i = blockIdx.x * 256 + threadIdx.x;
    float4 v = src[i];
    v.x = tf32r(v.x); v.y = tf32r(v.y); v.z = tf32r(v.z); v.w = tf32r(v.w);
    dst[i] = v;
}

// ---------------------------------------------------------------------------
extern "C" void kernel_launch(void* const* d_in, const int* in_sizes, int n_in,
                              void* d_out, int out_size)
{
    const float* x  = (const float*)d_in[0];
    const float* Wq = (const float*)d_in[1];
    const float* Wk = (const float*)d_in[2];
    const float* Wv = (const float*)d_in[3];
    float* out = (float*)d_out;

    (void)cudaFuncSetAttribute(mm_mma<0>, cudaFuncAttributeMaxDynamicSharedMemorySize, SMEM_DYN);
    (void)cudaFuncSetAttribute(mm_mma<1>, cudaFuncAttributeMaxDynamicSharedMemorySize, SMEM_DYN);
    (void)cudaFuncSetAttribute(mm_mma<2>, cudaFuncAttributeMaxDynamicSharedMemorySize, SMEM_DYN);
    (void)cudaFuncSetAttribute(mm_mma<3>, cudaFuncAttributeMaxDynamicSharedMemorySize, SMEM_DYN);
    (void)cudaFuncSetAttribute(mm_mma<4>, cudaFuncAttributeMaxDynamicSharedMemorySize, SMEM_DYN);

    float* gx = nullptr; float* gw = nullptr;
    cudaGetSymbolAddress((void**)&gx, g_x);
    cudaGetSymbolAddress((void**)&gw, g_w);

    dim3 blk(256);
    round4<<<(MT * DM / 4) / 256, blk>>>((const float4*)x, (float4*)gx);
    round4<<<(DM * DM / 4) / 256, blk>>>((const float4*)Wq, (float4*)gw);
    round4<<<(DM * DM / 4) / 256, blk>>>((const float4*)Wk, (float4*)(gw + (size_t)DM * DM));
    round4<<<(DM * DM / 4) / 256, blk>>>((const float4*)Wv, (float4*)(gw + (size_t)2 * DM * DM));

    dim3 gProj(DM / 128, MT / 128);            // (8, 64)
    mm_mma<0><<<gProj, blk, SMEM_DYN>>>(nullptr);
    mm_mma<1><<<gProj, blk, SMEM_DYN>>>(nullptr);
    mm_mma<2><<<gProj, blk, SMEM_DYN>>>(nullptr);

    dim3 gSc(SQ / 128, SQ / 128, BN);          // (16, 16, 4)
    mm_mma<3><<<gSc, blk, SMEM_DYN>>>(nullptr);

    rowsum_reduce<<<MT / 256, blk>>>();

    dim3 gPV(DM / 128, SQ / 128, BN);          // (8, 16, 4)
    mm_mma<4><<<gPV, blk, SMEM_DYN>>>(out);
}

// round 8
// speedup vs baseline: 6.5155x; 1.7787x over previous
#include <cuda_runtime.h>
#include <cuda_fp16.h>
#include <cstdint>

#define BN 4
#define SQ 2048
#define DM 1024
#define MT (BN * SQ)
#define BK 64
#define ASTR 72            // halves per A-tile row (128B data + 16B pad)
#define BSTR 136           // halves per trans-B-tile row (256B data + 16B pad)
#define ABYTES (128 * ASTR * 2)          // 18432
#define BBYTES 18432                     // max(64*136*2=17408, 128*72*2=18432)
#define STAGE (ABYTES + BBYTES)          // 36864
#define SMEM_DYN (2 * STAGE)             // 73728

// Scratch (__device__ globals; no allocation allowed)
__device__ __half g_x[(size_t)MT * DM];
__device__ __half g_w[(size_t)3 * DM * DM];
__device__ __half g_q[(size_t)MT * DM];
__device__ __half g_k[(size_t)MT * DM];
__device__ __half g_v[(size_t)MT * DM];
__device__ __half g_sc[(size_t)BN * SQ * SQ];   // unnormalized exp weights
__device__ float  g_lp[(size_t)MT * 64];        // row-sum partials
__device__ float  g_l[(size_t)MT];              // row sums

// ---------------------------------------------------------------------------
__device__ __forceinline__ uint32_t smem_u32(const void* p) {
    uint32_t a;
    asm("{ .reg .u64 t; cvta.to.shared.u64 t, %1; cvt.u32.u64 %0, t; }" : "=r"(a) : "l"(p));
    return a;
}

__device__ __forceinline__ uint32_t h2_u32(__half2 h) {
    return *reinterpret_cast<uint32_t*>(&h);
}

#define CP16(sa, g) \
    asm volatile("cp.async.cg.shared.global [%0], [%1], 16;" :: "r"(sa), "l"(g))
#define CP_COMMIT() asm volatile("cp.async.commit_group;" ::: "memory")
#define CP_WAIT1()  asm volatile("cp.async.wait_group 1;" ::: "memory")

#define LDSM4(r0, r1, r2, r3, addr) \
    asm volatile("ldmatrix.sync.aligned.m8n8.x4.shared.b16 {%0,%1,%2,%3}, [%4];" \
        : "=r"(r0), "=r"(r1), "=r"(r2), "=r"(r3) : "r"(addr))
#define LDSM4T(r0, r1, r2, r3, addr) \
    asm volatile("ldmatrix.sync.aligned.m8n8.x4.trans.shared.b16 {%0,%1,%2,%3}, [%4];" \
        : "=r"(r0), "=r"(r1), "=r"(r2), "=r"(r3) : "r"(addr))

__device__ __forceinline__ void mma_f16(float& c0, float& c1, float& c2, float& c3,
                                        uint32_t a0, uint32_t a1, uint32_t a2, uint32_t a3,
                                        uint32_t b0, uint32_t b1) {
    asm volatile(
        "mma.sync.aligned.m16n8k16.row.col.f32.f16.f16.f32 "
        "{%0,%1,%2,%3}, {%4,%5,%6,%7}, {%8,%9}, {%0,%1,%2,%3};"
        : "+f"(c0), "+f"(c1), "+f"(c2), "+f"(c3)
        : "r"(a0), "r"(a1), "r"(a2), "r"(a3), "r"(b0), "r"(b1));
}

// ---------------------------------------------------------------------------
// fp16 tensor-core GEMM, f32 accumulate, ldmatrix fragment loads.
// MODE: 0/1/2 = projections Q/K/V (B = W, n-major -> trans LDSM)
//       3 = scores QK^T (B = K rows, k-major -> no-trans LDSM; causal skip,
//           exp epilogue + row-sum partials)
//       4 = PV (B = V, n-major -> trans; causal K-trunc; normalize + out)
// CTA tile 128x128, BK=64, 256 threads; warp grid 2x4, warp tile 64x32.
// ---------------------------------------------------------------------------
template <int MODE>
__global__ __launch_bounds__(256) void mm_mma(float* __restrict__ Out)
{
    const int bx = blockIdx.x, bz = blockIdx.z;
    const int by = (MODE == 4) ? ((int)gridDim.y - 1 - (int)blockIdx.y)
                               : (int)blockIdx.y;
    if (MODE == 3 && bx > by) return;

    constexpr bool BTRANS = (MODE != 3);   // B via ldmatrix.trans (n-major src)

    const __half* Ab;
    const __half* Bb;
    size_t lda, ldb;
    int nt;
    if (MODE <= 2) {
        Ab = g_x + (size_t)by * 128 * DM;                         lda = DM;
        Bb = g_w + (size_t)MODE * DM * DM + bx * 128;             ldb = DM;  // [k][n]
        nt = DM / BK;
    } else if (MODE == 3) {
        Ab = g_q + ((size_t)bz * SQ + by * 128) * DM;             lda = DM;
        Bb = g_k + ((size_t)bz * SQ + bx * 128) * DM;             ldb = DM;  // [n][k]
        nt = DM / BK;
    } else {
        Ab = g_sc + ((size_t)bz * SQ + by * 128) * SQ;            lda = SQ;
        Bb = g_v + ((size_t)bz * SQ) * DM + bx * 128;             ldb = DM;  // [k][n]
        nt = (by + 1) * 2;
    }

    extern __shared__ char dsm[];
    const uint32_t sbase = smem_u32(dsm);

    const int tid = threadIdx.x;
    const int lane = tid & 31, wid = tid >> 5;
    const int wm = wid >> 2, wn = wid & 3;

    float acc[4][4][4];
#pragma unroll
    for (int i = 0; i < 4; ++i)
#pragma unroll
        for (int j = 0; j < 4; ++j)
#pragma unroll
            for (int r = 0; r < 4; ++r) acc[i][j][r] = 0.f;

    // ---- staging ---------------------------------------------------------
    auto stageA = [&](int kt, int buf) {
        const uint32_t abase = sbase + buf * STAGE;
#pragma unroll
        for (int u = 0; u < 4; ++u) {
            const int idx = tid + u * 256;          // 1024 16B chunks
            const int row = idx >> 3, c8 = idx & 7;
            CP16(abase + (uint32_t)(row * ASTR + c8 * 8) * 2,
                 Ab + (size_t)row * lda + kt * BK + c8 * 8);
        }
    };
    auto stageB = [&](int kt, int buf) {
        const uint32_t bbase = sbase + buf * STAGE + ABYTES;
        if (BTRANS) {
#pragma unroll
            for (int u = 0; u < 4; ++u) {
                const int idx = tid + u * 256;      // 64 rows x 16 chunks
                const int row = idx >> 4, c8 = idx & 15;
                CP16(bbase + (uint32_t)(row * BSTR + c8 * 8) * 2,
                     Bb + (size_t)(kt * BK + row) * ldb + c8 * 8);
            }
        } else {
#pragma unroll
            for (int u = 0; u < 4; ++u) {
                const int idx = tid + u * 256;      // 128 rows x 8 chunks
                const int row = idx >> 3, c8 = idx & 7;
                CP16(bbase + (uint32_t)(row * ASTR + c8 * 8) * 2,
                     Bb + (size_t)row * ldb + kt * BK + c8 * 8);
            }
        }
    };

    stageA(0, 0); stageB(0, 0);
    CP_COMMIT();

    // Per-thread ldmatrix address components
    const int a_row = wm * 64 + (lane & 15);
    const int a_col8 = (lane >> 4) << 3;
    // trans B: stored rows = k, cols = n
    const int bt_row = lane & 15;
    const int bt_col = wn * 32 + ((lane >> 4) << 3);
    // no-trans B (scores): stored rows = n, cols = k
    const int g4 = lane >> 3;
    const int bn_row = wn * 32 + ((g4 >> 1) << 3) + (lane & 7);
    const int bn_col8 = (g4 & 1) << 3;

    for (int kt = 0; kt < nt; ++kt) {
        if (kt + 1 < nt) { stageA(kt + 1, (kt + 1) & 1); stageB(kt + 1, (kt + 1) & 1); }
        CP_COMMIT();
        CP_WAIT1();
        __syncthreads();

        const uint32_t Abase = sbase + (kt & 1) * STAGE;
        const uint32_t Bbase = Abase + ABYTES;

#pragma unroll
        for (int ks = 0; ks < 4; ++ks) {
            uint32_t af[4][4];
#pragma unroll
            for (int ma = 0; ma < 4; ++ma) {
                const uint32_t ad = Abase +
                    (uint32_t)((a_row + ma * 16) * ASTR + ks * 16 + a_col8) * 2;
                LDSM4(af[ma][0], af[ma][1], af[ma][2], af[ma][3], ad);
            }
            uint32_t bf[4][2];
#pragma unroll
            for (int np = 0; np < 2; ++np) {
                uint32_t r0, r1, r2, r3;
                if (BTRANS) {
                    const uint32_t bd = Bbase +
                        (uint32_t)((ks * 16 + bt_row) * BSTR + bt_col + np * 16) * 2;
                    LDSM4T(r0, r1, r2, r3, bd);
                } else {
                    const uint32_t bd = Bbase +
                        (uint32_t)((bn_row + np * 16) * ASTR + ks * 16 + bn_col8) * 2;
                    LDSM4(r0, r1, r2, r3, bd);
                }
                bf[np * 2 + 0][0] = r0; bf[np * 2 + 0][1] = r1;
                bf[np * 2 + 1][0] = r2; bf[np * 2 + 1][1] = r3;
            }
#pragma unroll
            for (int ma = 0; ma < 4; ++ma)
#pragma unroll
                for (int na = 0; na < 4; ++na)
                    mma_f16(acc[ma][na][0], acc[ma][na][1], acc[ma][na][2], acc[ma][na][3],
                            af[ma][0], af[ma][1], af[ma][2], af[ma][3],
                            bf[na][0], bf[na][1]);
        }
        __syncthreads();
    }

    // ---- epilogue --------------------------------------------------------
    if (MODE == 3) {
        const float scale = 0.03125f;  // 1/sqrt(1024)
        __half* C = g_sc + (size_t)bz * SQ * SQ;
#pragma unroll
        for (int ma = 0; ma < 4; ++ma) {
            const int rl0 = by * 128 + wm * 64 + ma * 16 + (lane >> 2);
            const int rl1 = rl0 + 8;
            float part0 = 0.f, part1 = 0.f;
#pragma unroll
            for (int na = 0; na < 4; ++na) {
                const int c0 = bx * 128 + wn * 32 + na * 8 + (lane & 3) * 2;
                float p00 = __expf(acc[ma][na][0] * scale - 8.f);
                float p01 = __expf(acc[ma][na][1] * scale - 8.f);
                float p10 = __expf(acc[ma][na][2] * scale - 8.f);
                float p11 = __expf(acc[ma][na][3] * scale - 8.f);
                if (bx == by) {
                    if (c0     > rl0) p00 = 0.f;
                    if (c0 + 1 > rl0) p01 = 0.f;
                    if (c0     > rl1) p10 = 0.f;
                    if (c0 + 1 > rl1) p11 = 0.f;
                }
                __half h00 = __float2half_rn(p00), h01 = __float2half_rn(p01);
                __half h10 = __float2half_rn(p10), h11 = __float2half_rn(p11);
                part0 += __half2float(h00) + __half2float(h01);
                part1 += __half2float(h10) + __half2float(h11);
                *reinterpret_cast<__half2*>(C + (size_t)rl0 * SQ + c0) =
                    __halves2half2(h00, h01);
                *reinterpret_cast<__half2*>(C + (size_t)rl1 * SQ + c0) =
                    __halves2half2(h10, h11);
            }
            part0 += __shfl_xor_sync(0xffffffffu, part0, 1);
            part0 += __shfl_xor_sync(0xffffffffu, part0, 2);
            part1 += __shfl_xor_sync(0xffffffffu, part1, 1);
            part1 += __shfl_xor_sync(0xffffffffu, part1, 2);
            if ((lane & 3) == 0) {
                const int idx = bx * 4 + wn;
                g_lp[(size_t)(bz * SQ + rl0) * 64 + idx] = part0;
                g_lp[(size_t)(bz * SQ + rl1) * 64 + idx] = part1;
            }
        }
        return;
    }

#pragma unroll
    for (int ma = 0; ma < 4; ++ma) {
        const int r0 = by * 128 + wm * 64 + ma * 16 + (lane >> 2);
        float inv0 = 1.f, inv1 = 1.f;
        if (MODE == 4) {
            inv0 = __fdividef(1.f, g_l[bz * SQ + r0]);
            inv1 = __fdividef(1.f, g_l[bz * SQ + r0 + 8]);
        }
#pragma unroll
        for (int na = 0; na < 4; ++na) {
            const int c0 = bx * 128 + wn * 32 + na * 8 + (lane & 3) * 2;
            float v0 = acc[ma][na][0], v1 = acc[ma][na][1];
            float v2 = acc[ma][na][2], v3 = acc[ma][na][3];

            if (MODE <= 2) {
                __half* C = (MODE == 0) ? g_q : (MODE == 1) ? g_k : g_v;
                *reinterpret_cast<__half2*>(C + (size_t)r0 * DM + c0) =
                    __halves2half2(__float2half_rn(v0), __float2half_rn(v1));
                *reinterpret_cast<__half2*>(C + (size_t)(r0 + 8) * DM + c0) =
                    __halves2half2(__float2half_rn(v2), __float2half_rn(v3));
            } else {
                float* C = Out + (size_t)bz * SQ * DM;
                *reinterpret_cast<float2*>(C + (size_t)r0 * DM + c0) =
                    make_float2(v0 * inv0, v1 * inv0);
                *reinterpret_cast<float2*>(C + (size_t)(r0 + 8) * DM + c0) =
                    make_float2(v2 * inv1, v3 * inv1);
            }
        }
    }
}

// ---------------------------------------------------------------------------
// Deterministic row-sum reduce
// ---------------------------------------------------------------------------
__global__ __launch_bounds__(256) void rowsum_reduce()
{
    const int row = blockIdx.x * 256 + threadIdx.x;
    const int i = row & (SQ - 1);
    const int nvalid = ((i >> 7) + 1) * 4;
    const float* p = g_lp + (size_t)row * 64;
    float s = 0.f;
    for (int j = 0; j < nvalid; ++j) s += p[j];
    g_l[row] = s;
}

// ---------------------------------------------------------------------------
// fp32 -> fp16 conversion, 8 elems/thread
// ---------------------------------------------------------------------------
__global__ __launch_bounds__(256) void roundh(const float4* __restrict__ src,
                                              uint4* __restrict__ dst)
{
    const int i = blockIdx.x * 256 + threadIdx.x;
    float4 a = src[2 * i], b = src[2 * i + 1];
    __half2 h0 = __floats2half2_rn(a.x, a.y);
    __half2 h1 = __floats2half2_rn(a.z, a.w);
    __half2 h2 = __floats2half2_rn(b.x, b.y);
    __half2 h3 = __floats2half2_rn(b.z, b.w);
    uint4 o;
    o.x = *reinterpret_cast<uint32_t*>(&h0);
    o.y = *reinterpret_cast<uint32_t*>(&h1);
    o.z = *reinterpret_cast<uint32_t*>(&h2);
    o.w = *reinterpret_cast<uint32_t*>(&h3);
    dst[i] = o;
}

// ---------------------------------------------------------------------------
extern "C" void kernel_launch(void* const* d_in, const int* in_sizes, int n_in,
                              void* d_out, int out_size)
{
    const float* x  = (const float*)d_in[0];
    const float* Wq = (const float*)d_in[1];
    const float* Wk = (const float*)d_in[2];
    const float* Wv = (const float*)d_in[3];
    float* out = (float*)d_out;

    (void)cudaFuncSetAttribute(mm_mma<0>, cudaFuncAttributeMaxDynamicSharedMemorySize, SMEM_DYN);
    (void)cudaFuncSetAttribute(mm_mma<1>, cudaFuncAttributeMaxDynamicSharedMemorySize, SMEM_DYN);
    (void)cudaFuncSetAttribute(mm_mma<2>, cudaFuncAttributeMaxDynamicSharedMemorySize, SMEM_DYN);
    (void)cudaFuncSetAttribute(mm_mma<3>, cudaFuncAttributeMaxDynamicSharedMemorySize, SMEM_DYN);
    (void)cudaFuncSetAttribute(mm_mma<4>, cudaFuncAttributeMaxDynamicSharedMemorySize, SMEM_DYN);

    __half* gx = nullptr; __half* gw = nullptr;
    cudaGetSymbolAddress((void**)&gx, g_x);
    cudaGetSymbolAddress((void**)&gw, g_w);

    dim3 blk(256);
    roundh<<<(MT * DM / 8) / 256, blk>>>((const float4*)x, (uint4*)gx);
    roundh<<<(DM * DM / 8) / 256, blk>>>((const float4*)Wq, (uint4*)gw);
    roundh<<<(DM * DM / 8) / 256, blk>>>((const float4*)Wk, (uint4*)(gw + (size_t)DM * DM));
    roundh<<<(DM * DM / 8) / 256, blk>>>((const float4*)Wv, (uint4*)(gw + (size_t)2 * DM * DM));

    dim3 gProj(DM / 128, MT / 128);            // (8, 64)
    mm_mma<0><<<gProj, blk, SMEM_DYN>>>(nullptr);
    mm_mma<1><<<gProj, blk, SMEM_DYN>>>(nullptr);
    mm_mma<2><<<gProj, blk, SMEM_DYN>>>(nullptr);

    dim3 gSc(SQ / 128, SQ / 128, BN);          // (16, 16, 4)
    mm_mma<3><<<gSc, blk, SMEM_DYN>>>(nullptr);

    rowsum_reduce<<<MT / 256, blk>>>();

    dim3 gPV(DM / 128, SQ / 128, BN);          // (8, 16, 4)
    mm_mma<4><<<gPV, blk, SMEM_DYN>>>(out);
}

// round 9
// speedup vs baseline: 7.2182x; 1.1078x over previous
#include <cuda_runtime.h>
#include <cuda_fp16.h>
#include <cstdint>

#define BN 4
#define SQ 2048
#define DM 1024
#define MT (BN * SQ)
#define BK 64
#define ASTR 72            // halves per A-tile row (128B data + 16B pad)
#define BSTR 136           // halves per trans-B-tile row (256B data + 16B pad)
#define ABYTES (128 * ASTR * 2)          // 18432
#define BBYTES 18432                     // max(64*136*2, 128*72*2)
#define STAGE (ABYTES + BBYTES)          // 36864
#define NSTG 3
#define SMEM_DYN (NSTG * STAGE)          // 110592

// Scratch (__device__ globals; no allocation allowed)
__device__ __half g_x[(size_t)MT * DM];
__device__ __half g_w[(size_t)3 * DM * DM];
__device__ __half g_q[(size_t)MT * DM];
__device__ __half g_k[(size_t)MT * DM];
__device__ __half g_v[(size_t)MT * DM];
__device__ __half g_sc[(size_t)BN * SQ * SQ];   // unnormalized exp weights
__device__ float  g_lp[(size_t)MT * 64];        // row-sum partials
__device__ float  g_l[(size_t)MT];              // row sums

// ---------------------------------------------------------------------------
__device__ __forceinline__ uint32_t smem_u32(const void* p) {
    uint32_t a;
    asm("{ .reg .u64 t; cvta.to.shared.u64 t, %1; cvt.u32.u64 %0, t; }" : "=r"(a) : "l"(p));
    return a;
}

#define CP16(sa, g) \
    asm volatile("cp.async.cg.shared.global [%0], [%1], 16;" :: "r"(sa), "l"(g))
#define CP_COMMIT() asm volatile("cp.async.commit_group;" ::: "memory")
#define CP_WAITG1() asm volatile("cp.async.wait_group 1;" ::: "memory")

#define LDSM4(r0, r1, r2, r3, addr) \
    asm volatile("ldmatrix.sync.aligned.m8n8.x4.shared.b16 {%0,%1,%2,%3}, [%4];" \
        : "=r"(r0), "=r"(r1), "=r"(r2), "=r"(r3) : "r"(addr))
#define LDSM4T(r0, r1, r2, r3, addr) \
    asm volatile("ldmatrix.sync.aligned.m8n8.x4.trans.shared.b16 {%0,%1,%2,%3}, [%4];" \
        : "=r"(r0), "=r"(r1), "=r"(r2), "=r"(r3) : "r"(addr))

__device__ __forceinline__ void mma_f16(float& c0, float& c1, float& c2, float& c3,
                                        uint32_t a0, uint32_t a1, uint32_t a2, uint32_t a3,
                                        uint32_t b0, uint32_t b1) {
    asm volatile(
        "mma.sync.aligned.m16n8k16.row.col.f32.f16.f16.f32 "
        "{%0,%1,%2,%3}, {%4,%5,%6,%7}, {%8,%9}, {%0,%1,%2,%3};"
        : "+f"(c0), "+f"(c1), "+f"(c2), "+f"(c3)
        : "r"(a0), "r"(a1), "r"(a2), "r"(a3), "r"(b0), "r"(b1));
}

// ---------------------------------------------------------------------------
// fp16 tensor-core GEMM, f32 accumulate, ldmatrix fragment loads.
// MODE: 0 = merged projections QKV (bx/8 selects weight+dst; B trans LDSM)
//       3 = scores QK^T (B k-major, no-trans LDSM; causal skip, exp epilogue)
//       4 = PV (B = V n-major, trans; causal K-trunc; normalize + out)
// CTA tile 128x128, BK=64, 256 threads; warp grid 2x4, warp tile 64x32.
// 3-stage cp.async pipeline, one __syncthreads per k-iter.
// ---------------------------------------------------------------------------
template <int MODE>
__global__ __launch_bounds__(256, 2) void mm_mma(float* __restrict__ Out)
{
    const int bxr = blockIdx.x, bz = blockIdx.z;
    const int by = (MODE == 4) ? ((int)gridDim.y - 1 - (int)blockIdx.y)
                               : (int)blockIdx.y;
    if (MODE == 3 && bxr > by) return;

    const int which = (MODE == 0) ? (bxr >> 3) : 0;   // projection: 0=Q,1=K,2=V
    const int bx = (MODE == 0) ? (bxr & 7) : bxr;

    constexpr bool BTRANS = (MODE != 3);

    const __half* Ab;
    const __half* Bb;
    size_t lda, ldb;
    int nt;
    if (MODE == 0) {
        Ab = g_x + (size_t)by * 128 * DM;                         lda = DM;
        Bb = g_w + (size_t)which * DM * DM + bx * 128;            ldb = DM;  // [k][n]
        nt = DM / BK;
    } else if (MODE == 3) {
        Ab = g_q + ((size_t)bz * SQ + by * 128) * DM;             lda = DM;
        Bb = g_k + ((size_t)bz * SQ + bx * 128) * DM;             ldb = DM;  // [n][k]
        nt = DM / BK;
    } else {
        Ab = g_sc + ((size_t)bz * SQ + by * 128) * SQ;            lda = SQ;
        Bb = g_v + ((size_t)bz * SQ) * DM + bx * 128;             ldb = DM;  // [k][n]
        nt = (by + 1) * 2;
    }

    extern __shared__ char dsm[];
    const uint32_t sbase = smem_u32(dsm);

    const int tid = threadIdx.x;
    const int lane = tid & 31, wid = tid >> 5;
    const int wm = wid >> 2, wn = wid & 3;

    float acc[4][4][4];
#pragma unroll
    for (int i = 0; i < 4; ++i)
#pragma unroll
        for (int j = 0; j < 4; ++j)
#pragma unroll
            for (int r = 0; r < 4; ++r) acc[i][j][r] = 0.f;

    // ---- staging ---------------------------------------------------------
    auto stageA = [&](int kt, int buf) {
        const uint32_t abase = sbase + buf * STAGE;
#pragma unroll
        for (int u = 0; u < 4; ++u) {
            const int idx = tid + u * 256;          // 1024 16B chunks
            const int row = idx >> 3, c8 = idx & 7;
            CP16(abase + (uint32_t)(row * ASTR + c8 * 8) * 2,
                 Ab + (size_t)row * lda + kt * BK + c8 * 8);
        }
    };
    auto stageB = [&](int kt, int buf) {
        const uint32_t bbase = sbase + buf * STAGE + ABYTES;
        if (BTRANS) {
#pragma unroll
            for (int u = 0; u < 4; ++u) {
                const int idx = tid + u * 256;      // 64 rows x 16 chunks
                const int row = idx >> 4, c8 = idx & 15;
                CP16(bbase + (uint32_t)(row * BSTR + c8 * 8) * 2,
                     Bb + (size_t)(kt * BK + row) * ldb + c8 * 8);
            }
        } else {
#pragma unroll
            for (int u = 0; u < 4; ++u) {
                const int idx = tid + u * 256;      // 128 rows x 8 chunks
                const int row = idx >> 3, c8 = idx & 7;
                CP16(bbase + (uint32_t)(row * ASTR + c8 * 8) * 2,
                     Bb + (size_t)row * ldb + kt * BK + c8 * 8);
            }
        }
    };

    // Prologue: commit stages 0 and 1 as separate groups
    stageA(0, 0); stageB(0, 0);
    CP_COMMIT();
    if (1 < nt) { stageA(1, 1); stageB(1, 1); }
    CP_COMMIT();

    // Per-thread ldmatrix address components
    const int a_row = wm * 64 + (lane & 15);
    const int a_col8 = (lane >> 4) << 3;
    const int bt_row = lane & 15;
    const int bt_col = wn * 32 + ((lane >> 4) << 3);
    const int g4 = lane >> 3;
    const int bn_row = wn * 32 + ((g4 >> 1) << 3) + (lane & 7);
    const int bn_col8 = (g4 & 1) << 3;

    for (int kt = 0; kt < nt; ++kt) {
        // group kt complete (groups kt+1 may still be pending)
        CP_WAITG1();
        __syncthreads();   // kt data visible; all threads past compute(kt-1)

        // stage kt+2 into buffer (kt+2)%3 == (kt-1)%3 (safe after the sync)
        if (kt + 2 < nt) { stageA(kt + 2, (kt + 2) % NSTG); stageB(kt + 2, (kt + 2) % NSTG); }
        CP_COMMIT();

        const uint32_t Abase = sbase + (kt % NSTG) * STAGE;
        const uint32_t Bbase = Abase + ABYTES;

#pragma unroll
        for (int ks = 0; ks < 4; ++ks) {
            uint32_t af[4][4];
#pragma unroll
            for (int ma = 0; ma < 4; ++ma) {
                const uint32_t ad = Abase +
                    (uint32_t)((a_row + ma * 16) * ASTR + ks * 16 + a_col8) * 2;
                LDSM4(af[ma][0], af[ma][1], af[ma][2], af[ma][3], ad);
            }
            uint32_t bf[4][2];
#pragma unroll
            for (int np = 0; np < 2; ++np) {
                uint32_t r0, r1, r2, r3;
                if (BTRANS) {
                    const uint32_t bd = Bbase +
                        (uint32_t)((ks * 16 + bt_row) * BSTR + bt_col + np * 16) * 2;
                    LDSM4T(r0, r1, r2, r3, bd);
                } else {
                    const uint32_t bd = Bbase +
                        (uint32_t)((bn_row + np * 16) * ASTR + ks * 16 + bn_col8) * 2;
                    LDSM4(r0, r1, r2, r3, bd);
                }
                bf[np * 2 + 0][0] = r0; bf[np * 2 + 0][1] = r1;
                bf[np * 2 + 1][0] = r2; bf[np * 2 + 1][1] = r3;
            }
#pragma unroll
            for (int ma = 0; ma < 4; ++ma)
#pragma unroll
                for (int na = 0; na < 4; ++na)
                    mma_f16(acc[ma][na][0], acc[ma][na][1], acc[ma][na][2], acc[ma][na][3],
                            af[ma][0], af[ma][1], af[ma][2], af[ma][3],
                            bf[na][0], bf[na][1]);
        }
    }

    // ---- epilogue --------------------------------------------------------
    if (MODE == 3) {
        const float scale = 0.03125f;  // 1/sqrt(1024)
        __half* C = g_sc + (size_t)bz * SQ * SQ;
#pragma unroll
        for (int ma = 0; ma < 4; ++ma) {
            const int rl0 = by * 128 + wm * 64 + ma * 16 + (lane >> 2);
            const int rl1 = rl0 + 8;
            float part0 = 0.f, part1 = 0.f;
#pragma unroll
            for (int na = 0; na < 4; ++na) {
                const int c0 = bxr * 128 + wn * 32 + na * 8 + (lane & 3) * 2;
                float p00 = __expf(acc[ma][na][0] * scale - 8.f);
                float p01 = __expf(acc[ma][na][1] * scale - 8.f);
                float p10 = __expf(acc[ma][na][2] * scale - 8.f);
                float p11 = __expf(acc[ma][na][3] * scale - 8.f);
                if (bxr == by) {
                    if (c0     > rl0) p00 = 0.f;
                    if (c0 + 1 > rl0) p01 = 0.f;
                    if (c0     > rl1) p10 = 0.f;
                    if (c0 + 1 > rl1) p11 = 0.f;
                }
                __half h00 = __float2half_rn(p00), h01 = __float2half_rn(p01);
                __half h10 = __float2half_rn(p10), h11 = __float2half_rn(p11);
                part0 += __half2float(h00) + __half2float(h01);
                part1 += __half2float(h10) + __half2float(h11);
                *reinterpret_cast<__half2*>(C + (size_t)rl0 * SQ + c0) =
                    __halves2half2(h00, h01);
                *reinterpret_cast<__half2*>(C + (size_t)rl1 * SQ + c0) =
                    __halves2half2(h10, h11);
            }
            part0 += __shfl_xor_sync(0xffffffffu, part0, 1);
            part0 += __shfl_xor_sync(0xffffffffu, part0, 2);
            part1 += __shfl_xor_sync(0xffffffffu, part1, 1);
            part1 += __shfl_xor_sync(0xffffffffu, part1, 2);
            if ((lane & 3) == 0) {
                const int idx = bxr * 4 + wn;
                g_lp[(size_t)(bz * SQ + rl0) * 64 + idx] = part0;
                g_lp[(size_t)(bz * SQ + rl1) * 64 + idx] = part1;
            }
        }
        return;
    }

#pragma unroll
    for (int ma = 0; ma < 4; ++ma) {
        const int r0 = by * 128 + wm * 64 + ma * 16 + (lane >> 2);
        float inv0 = 1.f, inv1 = 1.f;
        if (MODE == 4) {
            inv0 = __fdividef(1.f, g_l[bz * SQ + r0]);
            inv1 = __fdividef(1.f, g_l[bz * SQ + r0 + 8]);
        }
#pragma unroll
        for (int na = 0; na < 4; ++na) {
            const int c0 = bx * 128 + wn * 32 + na * 8 + (lane & 3) * 2;
            float v0 = acc[ma][na][0], v1 = acc[ma][na][1];
            float v2 = acc[ma][na][2], v3 = acc[ma][na][3];

            if (MODE == 0) {
                __half* C = (which == 0) ? g_q : (which == 1) ? g_k : g_v;
                *reinterpret_cast<__half2*>(C + (size_t)r0 * DM + c0) =
                    __halves2half2(__float2half_rn(v0), __float2half_rn(v1));
                *reinterpret_cast<__half2*>(C + (size_t)(r0 + 8) * DM + c0) =
                    __halves2half2(__float2half_rn(v2), __float2half_rn(v3));
            } else {
                float* C = Out + (size_t)bz * SQ * DM;
                *reinterpret_cast<float2*>(C + (size_t)r0 * DM + c0) =
                    make_float2(v0 * inv0, v1 * inv0);
                *reinterpret_cast<float2*>(C + (size_t)(r0 + 8) * DM + c0) =
                    make_float2(v2 * inv1, v3 * inv1);
            }
        }
    }
}

// ---------------------------------------------------------------------------
// Deterministic row-sum reduce
// ---------------------------------------------------------------------------
__global__ __launch_bounds__(256) void rowsum_reduce()
{
    const int row = blockIdx.x * 256 + threadIdx.x;
    const int i = row & (SQ - 1);
    const int nvalid = ((i >> 7) + 1) * 4;
    const float* p = g_lp + (size_t)row * 64;
    float s = 0.f;
    for (int j = 0; j < nvalid; ++j) s += p[j];
    g_l[row] = s;
}

// ---------------------------------------------------------------------------
// fp32 -> fp16 conversion, 8 elems/thread
// ---------------------------------------------------------------------------
__global__ __launch_bounds__(256) void roundh(const float4* __restrict__ src,
                                              uint4* __restrict__ dst)
{
    const int i = blockIdx.x * 256 + threadIdx.x;
    float4 a = src[2 * i], b = src[2 * i + 1];
    __half2 h0 = __floats2half2_rn(a.x, a.y);
    __half2 h1 = __floats2half2_rn(a.z, a.w);
    __half2 h2 = __floats2half2_rn(b.x, b.y);
    __half2 h3 = __floats2half2_rn(b.z, b.w);
    uint4 o;
    o.x = *reinterpret_cast<uint32_t*>(&h0);
    o.y = *reinterpret_cast<uint32_t*>(&h1);
    o.z = *reinterpret_cast<uint32_t*>(&h2);
    o.w = *reinterpret_cast<uint32_t*>(&h3);
    dst[i] = o;
}

// ---------------------------------------------------------------------------
extern "C" void kernel_launch(void* const* d_in, const int* in_sizes, int n_in,
                              void* d_out, int out_size)
{
    const float* x  = (const float*)d_in[0];
    const float* Wq = (const float*)d_in[1];
    const float* Wk = (const float*)d_in[2];
    const float* Wv = (const float*)d_in[3];
    float* out = (float*)d_out;

    (void)cudaFuncSetAttribute(mm_mma<0>, cudaFuncAttributeMaxDynamicSharedMemorySize, SMEM_DYN);
    (void)cudaFuncSetAttribute(mm_mma<3>, cudaFuncAttributeMaxDynamicSharedMemorySize, SMEM_DYN);
    (void)cudaFuncSetAttribute(mm_mma<4>, cudaFuncAttributeMaxDynamicSharedMemorySize, SMEM_DYN);

    __half* gx = nullptr; __half* gw = nullptr;
    cudaGetSymbolAddress((void**)&gx, g_x);
    cudaGetSymbolAddress((void**)&gw, g_w);

    dim3 blk(256);
    roundh<<<(MT * DM / 8) / 256, blk>>>((const float4*)x, (uint4*)gx);
    roundh<<<(DM * DM / 8) / 256, blk>>>((const float4*)Wq, (uint4*)gw);
    roundh<<<(DM * DM / 8) / 256, blk>>>((const float4*)Wk, (uint4*)(gw + (size_t)DM * DM));
    roundh<<<(DM * DM / 8) / 256, blk>>>((const float4*)Wv, (uint4*)(gw + (size_t)2 * DM * DM));

    dim3 gProj(3 * DM / 128, MT / 128);        // (24, 64) merged QKV
    mm_mma<0><<<gProj, blk, SMEM_DYN>>>(nullptr);

    dim3 gSc(SQ / 128, SQ / 128, BN);          // (16, 16, 4)
    mm_mma<3><<<gSc, blk, SMEM_DYN>>>(nullptr);

    rowsum_reduce<<<MT / 256, blk>>>();

    dim3 gPV(DM / 128, SQ / 128, BN);          // (8, 16, 4)
    mm_mma<4><<<gPV, blk, SMEM_DYN>>>(out);
}

// round 10
// speedup vs baseline: 7.7136x; 1.0686x over previous
#include <cuda_runtime.h>
#include <cuda_fp16.h>
#include <cstdint>

#define BN 4
#define SQ 2048
#define DM 1024
#define MT (BN * SQ)
#define BK 64
#define ASTR 72            // halves per A-tile row (128B data + 16B pad)
#define BSTR 136           // halves per trans-B-tile row (256B data + 16B pad)
#define ABYTES (128 * ASTR * 2)          // 18432
#define BBYTES 18432                     // max(64*136*2, 128*72*2)
#define STAGE (ABYTES + BBYTES)          // 36864
#define NSTG 3
#define SMEM_DYN (NSTG * STAGE)          // 110592

// Scratch (__device__ globals; no allocation allowed)
__device__ __half g_x[(size_t)MT * DM];
__device__ __half g_w[(size_t)3 * DM * DM];
__device__ __half g_q[(size_t)MT * DM];
__device__ __half g_k[(size_t)MT * DM];
__device__ __half g_v[(size_t)MT * DM];
__device__ __half g_sc[(size_t)BN * SQ * SQ];   // unnormalized exp weights
__device__ float  g_lp[(size_t)MT * 64];        // row-sum partials
__device__ float  g_l[(size_t)MT];              // row sums

// ---------------------------------------------------------------------------
__device__ __forceinline__ uint32_t smem_u32(const void* p) {
    uint32_t a;
    asm("{ .reg .u64 t; cvta.to.shared.u64 t, %1; cvt.u32.u64 %0, t; }" : "=r"(a) : "l"(p));
    return a;
}

#define CP16(sa, g) \
    asm volatile("cp.async.cg.shared.global [%0], [%1], 16;" :: "r"(sa), "l"(g))
#define CP_COMMIT() asm volatile("cp.async.commit_group;" ::: "memory")
#define CP_WAITG1() asm volatile("cp.async.wait_group 1;" ::: "memory")

#define LDSM4(r0, r1, r2, r3, addr) \
    asm volatile("ldmatrix.sync.aligned.m8n8.x4.shared.b16 {%0,%1,%2,%3}, [%4];" \
        : "=r"(r0), "=r"(r1), "=r"(r2), "=r"(r3) : "r"(addr))
#define LDSM4T(r0, r1, r2, r3, addr) \
    asm volatile("ldmatrix.sync.aligned.m8n8.x4.trans.shared.b16 {%0,%1,%2,%3}, [%4];" \
        : "=r"(r0), "=r"(r1), "=r"(r2), "=r"(r3) : "r"(addr))

__device__ __forceinline__ void mma_f16(float& c0, float& c1, float& c2, float& c3,
                                        uint32_t a0, uint32_t a1, uint32_t a2, uint32_t a3,
                                        uint32_t b0, uint32_t b1) {
    asm volatile(
        "mma.sync.aligned.m16n8k16.row.col.f32.f16.f16.f32 "
        "{%0,%1,%2,%3}, {%4,%5,%6,%7}, {%8,%9}, {%0,%1,%2,%3};"
        : "+f"(c0), "+f"(c1), "+f"(c2), "+f"(c3)
        : "r"(a0), "r"(a1), "r"(a2), "r"(a3), "r"(b0), "r"(b1));
}

// ---------------------------------------------------------------------------
// GEMM body (device-inlined so block roles can be fused per launch).
// MODE: 0 = projection (which selects W/dst; B trans LDSM)
//       3 = scores QK^T (B k-major, no-trans LDSM; exp epilogue + partials)
//       4 = PV (B = V n-major, trans; causal K-trunc; normalize + out)
// CTA tile 128x128, BK=64, 256 threads; warp grid 2x4, warp tile 64x32.
// 3-stage cp.async pipeline, one __syncthreads per k-iter.
// ---------------------------------------------------------------------------
template <int MODE>
__device__ __forceinline__ void mm_body(int bx, int by, int bz, int which,
                                        float* __restrict__ Out, char* dsm)
{
    constexpr bool BTRANS = (MODE != 3);

    const __half* Ab;
    const __half* Bb;
    size_t lda, ldb;
    int nt;
    if (MODE == 0) {
        Ab = g_x + (size_t)by * 128 * DM;                         lda = DM;
        Bb = g_w + (size_t)which * DM * DM + bx * 128;            ldb = DM;  // [k][n]
        nt = DM / BK;
    } else if (MODE == 3) {
        Ab = g_q + ((size_t)bz * SQ + by * 128) * DM;             lda = DM;
        Bb = g_k + ((size_t)bz * SQ + bx * 128) * DM;             ldb = DM;  // [n][k]
        nt = DM / BK;
    } else {
        Ab = g_sc + ((size_t)bz * SQ + by * 128) * SQ;            lda = SQ;
        Bb = g_v + ((size_t)bz * SQ) * DM + bx * 128;             ldb = DM;  // [k][n]
        nt = (by + 1) * 2;
    }

    const uint32_t sbase = smem_u32(dsm);
    const int tid = threadIdx.x;
    const int lane = tid & 31, wid = tid >> 5;
    const int wm = wid >> 2, wn = wid & 3;

    float acc[4][4][4];
#pragma unroll
    for (int i = 0; i < 4; ++i)
#pragma unroll
        for (int j = 0; j < 4; ++j)
#pragma unroll
            for (int r = 0; r < 4; ++r) acc[i][j][r] = 0.f;

    auto stageA = [&](int kt, int buf) {
        const uint32_t abase = sbase + buf * STAGE;
#pragma unroll
        for (int u = 0; u < 4; ++u) {
            const int idx = tid + u * 256;
            const int row = idx >> 3, c8 = idx & 7;
            CP16(abase + (uint32_t)(row * ASTR + c8 * 8) * 2,
                 Ab + (size_t)row * lda + kt * BK + c8 * 8);
        }
    };
    auto stageB = [&](int kt, int buf) {
        const uint32_t bbase = sbase + buf * STAGE + ABYTES;
        if (BTRANS) {
#pragma unroll
            for (int u = 0; u < 4; ++u) {
                const int idx = tid + u * 256;
                const int row = idx >> 4, c8 = idx & 15;
                CP16(bbase + (uint32_t)(row * BSTR + c8 * 8) * 2,
                     Bb + (size_t)(kt * BK + row) * ldb + c8 * 8);
            }
        } else {
#pragma unroll
            for (int u = 0; u < 4; ++u) {
                const int idx = tid + u * 256;
                const int row = idx >> 3, c8 = idx & 7;
                CP16(bbase + (uint32_t)(row * ASTR + c8 * 8) * 2,
                     Bb + (size_t)row * ldb + kt * BK + c8 * 8);
            }
        }
    };

    stageA(0, 0); stageB(0, 0);
    CP_COMMIT();
    if (1 < nt) { stageA(1, 1); stageB(1, 1); }
    CP_COMMIT();

    const int a_row = wm * 64 + (lane & 15);
    const int a_col8 = (lane >> 4) << 3;
    const int bt_row = lane & 15;
    const int bt_col = wn * 32 + ((lane >> 4) << 3);
    const int g4 = lane >> 3;
    const int bn_row = wn * 32 + ((g4 >> 1) << 3) + (lane & 7);
    const int bn_col8 = (g4 & 1) << 3;

    for (int kt = 0; kt < nt; ++kt) {
        CP_WAITG1();
        __syncthreads();

        if (kt + 2 < nt) { stageA(kt + 2, (kt + 2) % NSTG); stageB(kt + 2, (kt + 2) % NSTG); }
        CP_COMMIT();

        const uint32_t Abase = sbase + (kt % NSTG) * STAGE;
        const uint32_t Bbase = Abase + ABYTES;

#pragma unroll
        for (int ks = 0; ks < 4; ++ks) {
            uint32_t af[4][4];
#pragma unroll
            for (int ma = 0; ma < 4; ++ma) {
                const uint32_t ad = Abase +
                    (uint32_t)((a_row + ma * 16) * ASTR + ks * 16 + a_col8) * 2;
                LDSM4(af[ma][0], af[ma][1], af[ma][2], af[ma][3], ad);
            }
            uint32_t bf[4][2];
#pragma unroll
            for (int np = 0; np < 2; ++np) {
                uint32_t r0, r1, r2, r3;
                if (BTRANS) {
                    const uint32_t bd = Bbase +
                        (uint32_t)((ks * 16 + bt_row) * BSTR + bt_col + np * 16) * 2;
                    LDSM4T(r0, r1, r2, r3, bd);
                } else {
                    const uint32_t bd = Bbase +
                        (uint32_t)((bn_row + np * 16) * ASTR + ks * 16 + bn_col8) * 2;
                    LDSM4(r0, r1, r2, r3, bd);
                }
                bf[np * 2 + 0][0] = r0; bf[np * 2 + 0][1] = r1;
                bf[np * 2 + 1][0] = r2; bf[np * 2 + 1][1] = r3;
            }
#pragma unroll
            for (int ma = 0; ma < 4; ++ma)
#pragma unroll
                for (int na = 0; na < 4; ++na)
                    mma_f16(acc[ma][na][0], acc[ma][na][1], acc[ma][na][2], acc[ma][na][3],
                            af[ma][0], af[ma][1], af[ma][2], af[ma][3],
                            bf[na][0], bf[na][1]);
        }
    }

    // ---- epilogue --------------------------------------------------------
    if (MODE == 3) {
        const float scale = 0.03125f;  // 1/sqrt(1024)
        __half* C = g_sc + (size_t)bz * SQ * SQ;
#pragma unroll
        for (int ma = 0; ma < 4; ++ma) {
            const int rl0 = by * 128 + wm * 64 + ma * 16 + (lane >> 2);
            const int rl1 = rl0 + 8;
            float part0 = 0.f, part1 = 0.f;
#pragma unroll
            for (int na = 0; na < 4; ++na) {
                const int c0 = bx * 128 + wn * 32 + na * 8 + (lane & 3) * 2;
                float p00 = __expf(acc[ma][na][0] * scale - 8.f);
                float p01 = __expf(acc[ma][na][1] * scale - 8.f);
                float p10 = __expf(acc[ma][na][2] * scale - 8.f);
                float p11 = __expf(acc[ma][na][3] * scale - 8.f);
                if (bx == by) {
                    if (c0     > rl0) p00 = 0.f;
                    if (c0 + 1 > rl0) p01 = 0.f;
                    if (c0     > rl1) p10 = 0.f;
                    if (c0 + 1 > rl1) p11 = 0.f;
                }
                __half h00 = __float2half_rn(p00), h01 = __float2half_rn(p01);
                __half h10 = __float2half_rn(p10), h11 = __float2half_rn(p11);
                part0 += __half2float(h00) + __half2float(h01);
                part1 += __half2float(h10) + __half2float(h11);
                *reinterpret_cast<__half2*>(C + (size_t)rl0 * SQ + c0) =
                    __halves2half2(h00, h01);
                *reinterpret_cast<__half2*>(C + (size_t)rl1 * SQ + c0) =
                    __halves2half2(h10, h11);
            }
            part0 += __shfl_xor_sync(0xffffffffu, part0, 1);
            part0 += __shfl_xor_sync(0xffffffffu, part0, 2);
            part1 += __shfl_xor_sync(0xffffffffu, part1, 1);
            part1 += __shfl_xor_sync(0xffffffffu, part1, 2);
            if ((lane & 3) == 0) {
                const int idx = bx * 4 + wn;
                g_lp[(size_t)(bz * SQ + rl0) * 64 + idx] = part0;
                g_lp[(size_t)(bz * SQ + rl1) * 64 + idx] = part1;
            }
        }
        return;
    }

#pragma unroll
    for (int ma = 0; ma < 4; ++ma) {
        const int r0 = by * 128 + wm * 64 + ma * 16 + (lane >> 2);
        float inv0 = 1.f, inv1 = 1.f;
        if (MODE == 4) {
            inv0 = __fdividef(1.f, g_l[bz * SQ + r0]);
            inv1 = __fdividef(1.f, g_l[bz * SQ + r0 + 8]);
        }
#pragma unroll
        for (int na = 0; na < 4; ++na) {
            const int c0 = bx * 128 + wn * 32 + na * 8 + (lane & 3) * 2;
            float v0 = acc[ma][na][0], v1 = acc[ma][na][1];
            float v2 = acc[ma][na][2], v3 = acc[ma][na][3];

            if (MODE == 0) {
                __half* C = (which == 0) ? g_q : (which == 1) ? g_k : g_v;
                *reinterpret_cast<__half2*>(C + (size_t)r0 * DM + c0) =
                    __halves2half2(__float2half_rn(v0), __float2half_rn(v1));
                *reinterpret_cast<__half2*>(C + (size_t)(r0 + 8) * DM + c0) =
                    __halves2half2(__float2half_rn(v2), __float2half_rn(v3));
            } else {
                float* C = Out + (size_t)bz * SQ * DM;
                *reinterpret_cast<float2*>(C + (size_t)r0 * DM + c0) =
                    make_float2(v0 * inv0, v1 * inv0);
                *reinterpret_cast<float2*>(C + (size_t)(r0 + 8) * DM + c0) =
                    make_float2(v2 * inv1, v3 * inv1);
            }
        }
    }
}

// ---------------------------------------------------------------------------
// Kernel wrappers
// ---------------------------------------------------------------------------
// Q and K projections, grid (16, 64): bx>>3 selects weight 0/1.
__global__ __launch_bounds__(256, 2) void k_proj_qk()
{
    extern __shared__ char dsm[];
    mm_body<0>((int)blockIdx.x & 7, (int)blockIdx.y, 0, (int)blockIdx.x >> 3,
               nullptr, dsm);
}

// Fused scores + V projection, grid (16, 16, 6):
//   bz < 4  -> scores block (bx, by, batch bz); skips if bx > by
//   bz >= 4 -> V-projection block id in [0, 512)
__global__ __launch_bounds__(256, 2) void k_scores_projv()
{
    extern __shared__ char dsm[];
    const int bx = blockIdx.x, by = blockIdx.y, bz = blockIdx.z;
    if (bz < 4) {
        if (bx > by) return;
        mm_body<3>(bx, by, bz, 0, nullptr, dsm);
    } else {
        const int id = (bz - 4) * 256 + by * 16 + bx;   // 0..511
        mm_body<0>(id & 7, id >> 3, 0, 2, nullptr, dsm);
    }
}

// PV, grid (8, 16, 4); heavy i-tiles first.
__global__ __launch_bounds__(256, 2) void k_pv(float* __restrict__ Out)
{
    extern __shared__ char dsm[];
    mm_body<4>((int)blockIdx.x, (int)gridDim.y - 1 - (int)blockIdx.y,
               (int)blockIdx.z, 0, Out, dsm);
}

// ---------------------------------------------------------------------------
// Deterministic row-sum reduce
// ---------------------------------------------------------------------------
__global__ __launch_bounds__(256) void rowsum_reduce()
{
    const int row = blockIdx.x * 256 + threadIdx.x;
    const int i = row & (SQ - 1);
    const int nvalid = ((i >> 7) + 1) * 4;
    const float* p = g_lp + (size_t)row * 64;
    float s = 0.f;
    for (int j = 0; j < nvalid; ++j) s += p[j];
    g_l[row] = s;
}

// ---------------------------------------------------------------------------
// fp32 -> fp16 conversion for x, Wq, Wk, Wv in ONE launch.
// Blocks [0, 4096)        -> x     (8M floats)
// Blocks [4096, 4608)     -> Wq    (1M floats)
// Blocks [4608, 5120)     -> Wk
// Blocks [5120, 5632)     -> Wv
// ---------------------------------------------------------------------------
__global__ __launch_bounds__(256) void roundh_all(
    const float4* __restrict__ x, const float4* __restrict__ Wq,
    const float4* __restrict__ Wk, const float4* __restrict__ Wv)
{
    const int bid = blockIdx.x;
    const float4* src;
    uint4* dst;
    int li;
    if (bid < 4096) {
        src = x;   dst = (uint4*)g_x;                         li = bid;
    } else if (bid < 4608) {
        src = Wq;  dst = (uint4*)g_w;                         li = bid - 4096;
    } else if (bid < 5120) {
        src = Wk;  dst = (uint4*)(g_w + (size_t)DM * DM);     li = bid - 4608;
    } else {
        src = Wv;  dst = (uint4*)(g_w + (size_t)2 * DM * DM); li = bid - 5120;
    }
    const int i = li * 256 + threadIdx.x;
    float4 a = src[2 * i], b = src[2 * i + 1];
    __half2 h0 = __floats2half2_rn(a.x, a.y);
    __half2 h1 = __floats2half2_rn(a.z, a.w);
    __half2 h2 = __floats2half2_rn(b.x, b.y);
    __half2 h3 = __floats2half2_rn(b.z, b.w);
    uint4 o;
    o.x = *reinterpret_cast<uint32_t*>(&h0);
    o.y = *reinterpret_cast<uint32_t*>(&h1);
    o.z = *reinterpret_cast<uint32_t*>(&h2);
    o.w = *reinterpret_cast<uint32_t*>(&h3);
    dst[i] = o;
}

// ---------------------------------------------------------------------------
extern "C" void kernel_launch(void* const* d_in, const int* in_sizes, int n_in,
                              void* d_out, int out_size)
{
    const float* x  = (const float*)d_in[0];
    const float* Wq = (const float*)d_in[1];
    const float* Wk = (const float*)d_in[2];
    const float* Wv = (const float*)d_in[3];
    float* out = (float*)d_out;

    (void)cudaFuncSetAttribute(k_proj_qk,
        cudaFuncAttributeMaxDynamicSharedMemorySize, SMEM_DYN);
    (void)cudaFuncSetAttribute(k_scores_projv,
        cudaFuncAttributeMaxDynamicSharedMemorySize, SMEM_DYN);
    (void)cudaFuncSetAttribute(k_pv,
        cudaFuncAttributeMaxDynamicSharedMemorySize, SMEM_DYN);

    dim3 blk(256);

    roundh_all<<<5632, blk>>>((const float4*)x, (const float4*)Wq,
                              (const float4*)Wk, (const float4*)Wv);

    dim3 gQK(16, 64);
    k_proj_qk<<<gQK, blk, SMEM_DYN>>>();

    dim3 gSV(16, 16, 6);
    k_scores_projv<<<gSV, blk, SMEM_DYN>>>();

    rowsum_reduce<<<MT / 256, blk>>>();

    dim3 gPV(8, 16, 4);
    k_pv<<<gPV, blk, SMEM_DYN>>>(out);
}

// round 11
// speedup vs baseline: 7.8739x; 1.0208x over previous
#include <cuda_runtime.h>
#include <cuda_fp16.h>
#include <cstdint>

#define BN 4
#define SQ 2048
#define DM 1024
#define MT (BN * SQ)
#define BK 64
#define ASTR 72            // halves per A-tile row (128B data + 16B pad)
#define BSTR 136           // halves per trans-B-tile row (256B data + 16B pad)
#define ABYTES (128 * ASTR * 2)          // 18432
#define BBYTES 18432                     // max(64*136*2, 128*72*2)
#define STAGE (ABYTES + BBYTES)          // 36864
#define NSTG 3
#define SMEM_DYN (NSTG * STAGE + 512)    // + row-sum buffer for PV

// Scratch (__device__ globals; no allocation allowed)
__device__ __half g_x[(size_t)MT * DM];
__device__ __half g_w[(size_t)3 * DM * DM];
__device__ __half g_q[(size_t)MT * DM];
__device__ __half g_k[(size_t)MT * DM];
__device__ __half g_v[(size_t)MT * DM];
__device__ __half g_sc[(size_t)BN * SQ * SQ];   // unnormalized exp weights
__device__ float  g_lp[(size_t)MT * 64];        // row-sum partials

// ---------------------------------------------------------------------------
__device__ __forceinline__ uint32_t smem_u32(const void* p) {
    uint32_t a;
    asm("{ .reg .u64 t; cvta.to.shared.u64 t, %1; cvt.u32.u64 %0, t; }" : "=r"(a) : "l"(p));
    return a;
}

#define CP16(sa, g) \
    asm volatile("cp.async.cg.shared.global [%0], [%1], 16;" :: "r"(sa), "l"(g))
#define CP_COMMIT() asm volatile("cp.async.commit_group;" ::: "memory")
#define CP_WAITG1() asm volatile("cp.async.wait_group 1;" ::: "memory")

#define LDSM4(r0, r1, r2, r3, addr) \
    asm volatile("ldmatrix.sync.aligned.m8n8.x4.shared.b16 {%0,%1,%2,%3}, [%4];" \
        : "=r"(r0), "=r"(r1), "=r"(r2), "=r"(r3) : "r"(addr))
#define LDSM4T(r0, r1, r2, r3, addr) \
    asm volatile("ldmatrix.sync.aligned.m8n8.x4.trans.shared.b16 {%0,%1,%2,%3}, [%4];" \
        : "=r"(r0), "=r"(r1), "=r"(r2), "=r"(r3) : "r"(addr))

__device__ __forceinline__ void mma_f16(float& c0, float& c1, float& c2, float& c3,
                                        uint32_t a0, uint32_t a1, uint32_t a2, uint32_t a3,
                                        uint32_t b0, uint32_t b1) {
    asm volatile(
        "mma.sync.aligned.m16n8k16.row.col.f32.f16.f16.f32 "
        "{%0,%1,%2,%3}, {%4,%5,%6,%7}, {%8,%9}, {%0,%1,%2,%3};"
        : "+f"(c0), "+f"(c1), "+f"(c2), "+f"(c3)
        : "r"(a0), "r"(a1), "r"(a2), "r"(a3), "r"(b0), "r"(b1));
}

// ---------------------------------------------------------------------------
// GEMM body. MODE: 0 = projection; 3 = scores (exp epilogue + partials);
// 4 = PV (fused row-sum prologue, normalize, write out).
// CTA tile 128x128, BK=64, 256 threads; warp grid 2x4, warp tile 64x32.
// 3-stage cp.async pipeline, one __syncthreads per k-iter.
// ---------------------------------------------------------------------------
template <int MODE>
__device__ __forceinline__ void mm_body(int bx, int by, int bz, int which,
                                        float* __restrict__ Out, char* dsm)
{
    constexpr bool BTRANS = (MODE != 3);

    const __half* Ab;
    const __half* Bb;
    size_t lda, ldb;
    int nt;
    if (MODE == 0) {
        Ab = g_x + (size_t)by * 128 * DM;                         lda = DM;
        Bb = g_w + (size_t)which * DM * DM + bx * 128;            ldb = DM;  // [k][n]
        nt = DM / BK;
    } else if (MODE == 3) {
        Ab = g_q + ((size_t)bz * SQ + by * 128) * DM;             lda = DM;
        Bb = g_k + ((size_t)bz * SQ + bx * 128) * DM;             ldb = DM;  // [n][k]
        nt = DM / BK;
    } else {
        Ab = g_sc + ((size_t)bz * SQ + by * 128) * SQ;            lda = SQ;
        Bb = g_v + ((size_t)bz * SQ) * DM + bx * 128;             ldb = DM;  // [k][n]
        nt = (by + 1) * 2;
    }

    const uint32_t sbase = smem_u32(dsm);
    float* s_l = reinterpret_cast<float*>(dsm + NSTG * STAGE);  // 128 row sums (PV)
    const int tid = threadIdx.x;
    const int lane = tid & 31, wid = tid >> 5;
    const int wm = wid >> 2, wn = wid & 3;

    float acc[4][4][4];
#pragma unroll
    for (int i = 0; i < 4; ++i)
#pragma unroll
        for (int j = 0; j < 4; ++j)
#pragma unroll
            for (int r = 0; r < 4; ++r) acc[i][j][r] = 0.f;

    auto stageA = [&](int kt, int buf) {
        const uint32_t abase = sbase + buf * STAGE;
#pragma unroll
        for (int u = 0; u < 4; ++u) {
            const int idx = tid + u * 256;
            const int row = idx >> 3, c8 = idx & 7;
            CP16(abase + (uint32_t)(row * ASTR + c8 * 8) * 2,
                 Ab + (size_t)row * lda + kt * BK + c8 * 8);
        }
    };
    auto stageB = [&](int kt, int buf) {
        const uint32_t bbase = sbase + buf * STAGE + ABYTES;
        if (BTRANS) {
#pragma unroll
            for (int u = 0; u < 4; ++u) {
                const int idx = tid + u * 256;
                const int row = idx >> 4, c8 = idx & 15;
                CP16(bbase + (uint32_t)(row * BSTR + c8 * 8) * 2,
                     Bb + (size_t)(kt * BK + row) * ldb + c8 * 8);
            }
        } else {
#pragma unroll
            for (int u = 0; u < 4; ++u) {
                const int idx = tid + u * 256;
                const int row = idx >> 3, c8 = idx & 7;
                CP16(bbase + (uint32_t)(row * ASTR + c8 * 8) * 2,
                     Bb + (size_t)row * ldb + kt * BK + c8 * 8);
            }
        }
    };

    stageA(0, 0); stageB(0, 0);
    CP_COMMIT();
    if (1 < nt) { stageA(1, 1); stageB(1, 1); }
    CP_COMMIT();

    // PV: fused row-sum reduce, overlapped with the in-flight cp.async stages.
    // Threads 0..127 each own one local row; float4 loads with sequential adds
    // preserve the exact serial accumulation order of the old reduce kernel.
    if (MODE == 4) {
        if (tid < 128) {
            const int row = bz * SQ + by * 128 + tid;
            const int nvalid4 = (by + 1);            // nvalid = (by+1)*4 floats
            const float4* p = reinterpret_cast<const float4*>(g_lp + (size_t)row * 64);
            float s = 0.f;
            for (int j = 0; j < nvalid4; ++j) {
                float4 v = p[j];
                s += v.x; s += v.y; s += v.z; s += v.w;
            }
            s_l[tid] = s;
        }
        // visibility guaranteed by the __syncthreads at top of first k-iter
    }

    const int a_row = wm * 64 + (lane & 15);
    const int a_col8 = (lane >> 4) << 3;
    const int bt_row = lane & 15;
    const int bt_col = wn * 32 + ((lane >> 4) << 3);
    const int g4 = lane >> 3;
    const int bn_row = wn * 32 + ((g4 >> 1) << 3) + (lane & 7);
    const int bn_col8 = (g4 & 1) << 3;

    for (int kt = 0; kt < nt; ++kt) {
        CP_WAITG1();
        __syncthreads();

        if (kt + 2 < nt) { stageA(kt + 2, (kt + 2) % NSTG); stageB(kt + 2, (kt + 2) % NSTG); }
        CP_COMMIT();

        const uint32_t Abase = sbase + (kt % NSTG) * STAGE;
        const uint32_t Bbase = Abase + ABYTES;

#pragma unroll
        for (int ks = 0; ks < 4; ++ks) {
            uint32_t af[4][4];
#pragma unroll
            for (int ma = 0; ma < 4; ++ma) {
                const uint32_t ad = Abase +
                    (uint32_t)((a_row + ma * 16) * ASTR + ks * 16 + a_col8) * 2;
                LDSM4(af[ma][0], af[ma][1], af[ma][2], af[ma][3], ad);
            }
            uint32_t bf[4][2];
#pragma unroll
            for (int np = 0; np < 2; ++np) {
                uint32_t r0, r1, r2, r3;
                if (BTRANS) {
                    const uint32_t bd = Bbase +
                        (uint32_t)((ks * 16 + bt_row) * BSTR + bt_col + np * 16) * 2;
                    LDSM4T(r0, r1, r2, r3, bd);
                } else {
                    const uint32_t bd = Bbase +
                        (uint32_t)((bn_row + np * 16) * ASTR + ks * 16 + bn_col8) * 2;
                    LDSM4(r0, r1, r2, r3, bd);
                }
                bf[np * 2 + 0][0] = r0; bf[np * 2 + 0][1] = r1;
                bf[np * 2 + 1][0] = r2; bf[np * 2 + 1][1] = r3;
            }
#pragma unroll
            for (int ma = 0; ma < 4; ++ma)
#pragma unroll
                for (int na = 0; na < 4; ++na)
                    mma_f16(acc[ma][na][0], acc[ma][na][1], acc[ma][na][2], acc[ma][na][3],
                            af[ma][0], af[ma][1], af[ma][2], af[ma][3],
                            bf[na][0], bf[na][1]);
        }
    }

    // ---- epilogue --------------------------------------------------------
    if (MODE == 3) {
        const float scale = 0.03125f;  // 1/sqrt(1024)
        __half* C = g_sc + (size_t)bz * SQ * SQ;
#pragma unroll
        for (int ma = 0; ma < 4; ++ma) {
            const int rl0 = by * 128 + wm * 64 + ma * 16 + (lane >> 2);
            const int rl1 = rl0 + 8;
            float part0 = 0.f, part1 = 0.f;
#pragma unroll
            for (int na = 0; na < 4; ++na) {
                const int c0 = bx * 128 + wn * 32 + na * 8 + (lane & 3) * 2;
                float p00 = __expf(acc[ma][na][0] * scale - 8.f);
                float p01 = __expf(acc[ma][na][1] * scale - 8.f);
                float p10 = __expf(acc[ma][na][2] * scale - 8.f);
                float p11 = __expf(acc[ma][na][3] * scale - 8.f);
                if (bx == by) {
                    if (c0     > rl0) p00 = 0.f;
                    if (c0 + 1 > rl0) p01 = 0.f;
                    if (c0     > rl1) p10 = 0.f;
                    if (c0 + 1 > rl1) p11 = 0.f;
                }
                __half h00 = __float2half_rn(p00), h01 = __float2half_rn(p01);
                __half h10 = __float2half_rn(p10), h11 = __float2half_rn(p11);
                part0 += __half2float(h00) + __half2float(h01);
                part1 += __half2float(h10) + __half2float(h11);
                *reinterpret_cast<__half2*>(C + (size_t)rl0 * SQ + c0) =
                    __halves2half2(h00, h01);
                *reinterpret_cast<__half2*>(C + (size_t)rl1 * SQ + c0) =
                    __halves2half2(h10, h11);
            }
            part0 += __shfl_xor_sync(0xffffffffu, part0, 1);
            part0 += __shfl_xor_sync(0xffffffffu, part0, 2);
            part1 += __shfl_xor_sync(0xffffffffu, part1, 1);
            part1 += __shfl_xor_sync(0xffffffffu, part1, 2);
            if ((lane & 3) == 0) {
                const int idx = bx * 4 + wn;
                g_lp[(size_t)(bz * SQ + rl0) * 64 + idx] = part0;
                g_lp[(size_t)(bz * SQ + rl1) * 64 + idx] = part1;
            }
        }
        return;
    }

#pragma unroll
    for (int ma = 0; ma < 4; ++ma) {
        const int lr0 = wm * 64 + ma * 16 + (lane >> 2);
        const int r0 = by * 128 + lr0;
        float inv0 = 1.f, inv1 = 1.f;
        if (MODE == 4) {
            inv0 = __fdividef(1.f, s_l[lr0]);
            inv1 = __fdividef(1.f, s_l[lr0 + 8]);
        }
#pragma unroll
        for (int na = 0; na < 4; ++na) {
            const int c0 = bx * 128 + wn * 32 + na * 8 + (lane & 3) * 2;
            float v0 = acc[ma][na][0], v1 = acc[ma][na][1];
            float v2 = acc[ma][na][2], v3 = acc[ma][na][3];

            if (MODE == 0) {
                __half* C = (which == 0) ? g_q : (which == 1) ? g_k : g_v;
                *reinterpret_cast<__half2*>(C + (size_t)r0 * DM + c0) =
                    __halves2half2(__float2half_rn(v0), __float2half_rn(v1));
                *reinterpret_cast<__half2*>(C + (size_t)(r0 + 8) * DM + c0) =
                    __halves2half2(__float2half_rn(v2), __float2half_rn(v3));
            } else {
                float* C = Out + (size_t)bz * SQ * DM;
                *reinterpret_cast<float2*>(C + (size_t)r0 * DM + c0) =
                    make_float2(v0 * inv0, v1 * inv0);
                *reinterpret_cast<float2*>(C + (size_t)(r0 + 8) * DM + c0) =
                    make_float2(v2 * inv1, v3 * inv1);
            }
        }
    }
}

// ---------------------------------------------------------------------------
// Kernel wrappers
// ---------------------------------------------------------------------------
__global__ __launch_bounds__(256, 2) void k_proj_qk()
{
    extern __shared__ char dsm[];
    mm_body<0>((int)blockIdx.x & 7, (int)blockIdx.y, 0, (int)blockIdx.x >> 3,
               nullptr, dsm);
}

// Fused scores + V projection, grid (16, 16, 6)
__global__ __launch_bounds__(256, 2) void k_scores_projv()
{
    extern __shared__ char dsm[];
    const int bx = blockIdx.x, by = blockIdx.y, bz = blockIdx.z;
    if (bz < 4) {
        if (bx > by) return;
        mm_body<3>(bx, by, bz, 0, nullptr, dsm);
    } else {
        const int id = (bz - 4) * 256 + by * 16 + bx;   // 0..511
        mm_body<0>(id & 7, id >> 3, 0, 2, nullptr, dsm);
    }
}

// PV with fused row-sum; heavy i-tiles first.
__global__ __launch_bounds__(256, 2) void k_pv(float* __restrict__ Out)
{
    extern __shared__ char dsm[];
    mm_body<4>((int)blockIdx.x, (int)gridDim.y - 1 - (int)blockIdx.y,
               (int)blockIdx.z, 0, Out, dsm);
}

// ---------------------------------------------------------------------------
// fp32 -> fp16 conversion, 16 elems/thread, 4 independent loads in flight.
// Blocks [0, 2048)   -> x   (8M floats)
// Blocks [2048, 2304)-> Wq, [2304, 2560) -> Wk, [2560, 2816) -> Wv
// ---------------------------------------------------------------------------
__global__ __launch_bounds__(256) void roundh_all(
    const float4* __restrict__ x, const float4* __restrict__ Wq,
    const float4* __restrict__ Wk, const float4* __restrict__ Wv)
{
    const int bid = blockIdx.x;
    const float4* src;
    uint4* dst;
    int li;
    if (bid < 2048) {
        src = x;   dst = (uint4*)g_x;                         li = bid;
    } else if (bid < 2304) {
        src = Wq;  dst = (uint4*)g_w;                         li = bid - 2048;
    } else if (bid < 2560) {
        src = Wk;  dst = (uint4*)(g_w + (size_t)DM * DM);     li = bid - 2304;
    } else {
        src = Wv;  dst = (uint4*)(g_w + (size_t)2 * DM * DM); li = bid - 2560;
    }
    const int i = li * 256 + threadIdx.x;      // uint4-output index base (x2)
    float4 a0 = src[4 * i + 0];
    float4 a1 = src[4 * i + 1];
    float4 a2 = src[4 * i + 2];
    float4 a3 = src[4 * i + 3];
    __half2 h0 = __floats2half2_rn(a0.x, a0.y);
    __half2 h1 = __floats2half2_rn(a0.z, a0.w);
    __half2 h2 = __floats2half2_rn(a1.x, a1.y);
    __half2 h3 = __floats2half2_rn(a1.z, a1.w);
    __half2 h4 = __floats2half2_rn(a2.x, a2.y);
    __half2 h5 = __floats2half2_rn(a2.z, a2.w);
    __half2 h6 = __floats2half2_rn(a3.x, a3.y);
    __half2 h7 = __floats2half2_rn(a3.z, a3.w);
    uint4 o0, o1;
    o0.x = *reinterpret_cast<uint32_t*>(&h0);
    o0.y = *reinterpret_cast<uint32_t*>(&h1);
    o0.z = *reinterpret_cast<uint32_t*>(&h2);
    o0.w = *reinterpret_cast<uint32_t*>(&h3);
    o1.x = *reinterpret_cast<uint32_t*>(&h4);
    o1.y = *reinterpret_cast<uint32_t*>(&h5);
    o1.z = *reinterpret_cast<uint32_t*>(&h6);
    o1.w = *reinterpret_cast<uint32_t*>(&h7);
    dst[2 * i + 0] = o0;
    dst[2 * i + 1] = o1;
}

// ---------------------------------------------------------------------------
extern "C" void kernel_launch(void* const* d_in, const int* in_sizes, int n_in,
                              void* d_out, int out_size)
{
    const float* x  = (const float*)d_in[0];
    const float* Wq = (const float*)d_in[1];
    const float* Wk = (const float*)d_in[2];
    const float* Wv = (const float*)d_in[3];
    float* out = (float*)d_out;

    (void)cudaFuncSetAttribute(k_proj_qk,
        cudaFuncAttributeMaxDynamicSharedMemorySize, SMEM_DYN);
    (void)cudaFuncSetAttribute(k_scores_projv,
        cudaFuncAttributeMaxDynamicSharedMemorySize, SMEM_DYN);
    (void)cudaFuncSetAttribute(k_pv,
        cudaFuncAttributeMaxDynamicSharedMemorySize, SMEM_DYN);

    dim3 blk(256);

    roundh_all<<<2816, blk>>>((const float4*)x, (const float4*)Wq,
                              (const float4*)Wk, (const float4*)Wv);

    dim3 gQK(16, 64);
    k_proj_qk<<<gQK, blk, SMEM_DYN>>>();

    dim3 gSV(16, 16, 6);
    k_scores_projv<<<gSV, blk, SMEM_DYN>>>();

    dim3 gPV(8, 16, 4);
    k_pv<<<gPV, blk, SMEM_DYN>>>(out);
}